// round 7
// baseline (speedup 1.0000x reference)
#include <cuda_runtime.h>
#include <cuda_bf16.h>

#define BB 2
#define SEQL 2048
#define DD 256
#define HH 8
#define DKK 32
#define DFFN 1024
#define EPSF 1e-5f

#define NH  (BB*SEQL*DD)      /* 1048576 */
#define NFF (BB*SEQL*DFFN)    /* 4194304 */

#define BF16_FLOATS 8912896L
__device__ float g_buf[7L*NH + BF16_FLOATS + 512 + 16384];

__device__ __forceinline__ int compute_kcut(float tdh) {
    if (!(tdh > 1e-6f)) return SEQL;
    float c = 33.0f / tdh;     // exp(s * e^-33) == 1.0f exactly for |s| < 1e7
    if (c >= (float)SEQL) return SEQL;
    int k = (int)ceilf(c);
    return k < SEQL ? k : SEQL;
}

// ---------------------------------------------------------------- conv + bn + relu + pe (+ bf16 split)
__global__ void conv_pe_kernel(const float* __restrict__ x, const float* __restrict__ cw,
                               const float* __restrict__ cb, const float* __restrict__ bg,
                               const float* __restrict__ bb, const float* __restrict__ pe,
                               float* __restrict__ out,
                               __nv_bfloat16* __restrict__ oh, __nv_bfloat16* __restrict__ ol) {
    int idx = blockIdx.x * 256 + threadIdx.x;
    if (idx >= NH) return;
    int d = idx & (DD - 1);
    int t = (idx >> 8) & (SEQL - 1);
    int b = idx >> 19;
    const float* xb = x + b * SEQL;
    float xm = t > 0 ? xb[t - 1] : 0.f;
    float x0 = xb[t];
    float xp = (t < SEQL - 1) ? xb[t + 1] : 0.f;
    float v = cw[d * 3 + 0] * xm + cw[d * 3 + 1] * x0 + cw[d * 3 + 2] * xp + cb[d];
    v = v * rsqrtf(1.f + EPSF) * bg[d] + bb[d];
    v = fmaxf(v, 0.f);
    float r = v + pe[t * DD + d];
    out[idx] = r;
    __nv_bfloat16 h = __float2bfloat16(r);
    oh[idx] = h;
    ol[idx] = __float2bfloat16(r - __bfloat162float(h));
}

// ---------------------------------------------------------------- weight split fp32 -> bf16 hi/lo
__global__ void wsplit_kernel(const float* __restrict__ q, const float* __restrict__ k,
                              const float* __restrict__ v, const float* __restrict__ o,
                              const float* __restrict__ f1, const float* __restrict__ f2,
                              __nv_bfloat16* __restrict__ W) {
    int z = blockIdx.z;
    const float* src; long n; long off;
    switch (z) {
        case 0: src = q;  n = 131072; off = 0;       break;
        case 1: src = k;  n = 131072; off = 262144;  break;
        case 2: src = v;  n = 131072; off = 524288;  break;
        case 3: src = o;  n = 131072; off = 786432;  break;
        case 4: src = f1; n = 524288; off = 1048576; break;
        default: src = f2; n = 524288; off = 2097152; break;
    }
    __nv_bfloat16* dh = W + off;
    __nv_bfloat16* dl = dh + n;
    for (long i = blockIdx.x * 256L + threadIdx.x; i < n; i += (long)gridDim.x * 256L) {
        float xx = src[i];
        __nv_bfloat16 h = __float2bfloat16(xx);
        dh[i] = h;
        dl[i] = __float2bfloat16(xx - __bfloat162float(h));
    }
}

// ---------------------------------------------------------------- HMMA GEMM: C[M,N] = A[M,K] @ W[N,K]^T
struct TcJob {
    const __nv_bfloat16 *Ah, *Al;
    const __nv_bfloat16 *Wh, *Wl;
    const float* bias;
    float* C;
    __nv_bfloat16 *Ch, *Cl;
    const float* tdl;            // if set: CTA exits when (m0 & (SEQL-1)) >= max kcut
    int lda, ldw, N, K, flags;   // flags: 1=RELU 2=FP32OUT 4=BF16OUT 8=BIAS
};
struct TcJobs3 { TcJob j[3]; };

#define MMA_BF16(c, a, b) \
    asm volatile("mma.sync.aligned.m16n8k16.row.col.f32.bf16.bf16.f32 " \
        "{%0,%1,%2,%3}, {%4,%5,%6,%7}, {%8,%9}, {%0,%1,%2,%3};" \
        : "+f"((c)[0]), "+f"((c)[1]), "+f"((c)[2]), "+f"((c)[3]) \
        : "r"((a)[0]), "r"((a)[1]), "r"((a)[2]), "r"((a)[3]), "r"((b)[0]), "r"((b)[1]))

#define LDU(p) (*(const unsigned*)(p))

__global__ __launch_bounds__(256) void tc_kernel(TcJobs3 jobs) {
    TcJob jb = jobs.j[blockIdx.z];
    const int m0 = blockIdx.y * 128, n0 = blockIdx.x * 64;
    if (jb.tdl) {
        int kmax = 0;
#pragma unroll
        for (int h = 0; h < HH; h++) {
            int kc = compute_kcut(jb.tdl[h]);
            kmax = kc > kmax ? kc : kmax;
        }
        if ((m0 & (SEQL - 1)) >= kmax) return;   // rows unused downstream
    }
    __shared__ __nv_bfloat16 sA[2][128][40];   // [hi/lo][row][k+pad]
    __shared__ __nv_bfloat16 sB[2][64][40];
    const int tid = threadIdx.x, wid = tid >> 5, lane = tid & 31;
    const int wm = (wid & 3) * 32, wn = (wid >> 2) * 32;
    const int g = lane >> 2, tg = lane & 3;

    float acc[2][4][4];
#pragma unroll
    for (int mi = 0; mi < 2; mi++)
#pragma unroll
        for (int ni = 0; ni < 4; ni++)
#pragma unroll
            for (int r = 0; r < 4; r++) acc[mi][ni][r] = 0.f;

    const int brow = tid >> 2, bc8 = tid & 3;
    uint4 ra_h[2], ra_l[2], rb_h, rb_l;

    auto loadg = [&](int kb) {
#pragma unroll
        for (int i = 0; i < 2; i++) {
            int idx = i * 256 + tid;
            int rr = idx >> 2, cc = idx & 3;
            size_t go = (size_t)(m0 + rr) * jb.lda + kb + cc * 8;
            ra_h[i] = *(const uint4*)(jb.Ah + go);
            ra_l[i] = *(const uint4*)(jb.Al + go);
        }
        size_t go = (size_t)(n0 + brow) * jb.ldw + kb + bc8 * 8;
        rb_h = *(const uint4*)(jb.Wh + go);
        rb_l = *(const uint4*)(jb.Wl + go);
    };

    loadg(0);
    for (int kb = 0; kb < jb.K; kb += 32) {
        __syncthreads();
#pragma unroll
        for (int i = 0; i < 2; i++) {
            int idx = i * 256 + tid;
            int rr = idx >> 2, cc = idx & 3;
            *(uint4*)&sA[0][rr][cc * 8] = ra_h[i];
            *(uint4*)&sA[1][rr][cc * 8] = ra_l[i];
        }
        *(uint4*)&sB[0][brow][bc8 * 8] = rb_h;
        *(uint4*)&sB[1][brow][bc8 * 8] = rb_l;
        __syncthreads();
        if (kb + 32 < jb.K) loadg(kb + 32);   // prefetch overlapped with MMA below

#pragma unroll
        for (int ks = 0; ks < 2; ks++) {
            const int k0 = ks * 16;
            unsigned ah[2][4], al[2][4];
#pragma unroll
            for (int mi = 0; mi < 2; mi++) {
                int r = wm + mi * 16 + g;
                ah[mi][0] = LDU(&sA[0][r][k0 + 2 * tg]);
                ah[mi][1] = LDU(&sA[0][r + 8][k0 + 2 * tg]);
                ah[mi][2] = LDU(&sA[0][r][k0 + 2 * tg + 8]);
                ah[mi][3] = LDU(&sA[0][r + 8][k0 + 2 * tg + 8]);
                al[mi][0] = LDU(&sA[1][r][k0 + 2 * tg]);
                al[mi][1] = LDU(&sA[1][r + 8][k0 + 2 * tg]);
                al[mi][2] = LDU(&sA[1][r][k0 + 2 * tg + 8]);
                al[mi][3] = LDU(&sA[1][r + 8][k0 + 2 * tg + 8]);
            }
            unsigned bh[4][2], bl[4][2];
#pragma unroll
            for (int ni = 0; ni < 4; ni++) {
                int rn = wn + ni * 8 + g;
                bh[ni][0] = LDU(&sB[0][rn][k0 + 2 * tg]);
                bh[ni][1] = LDU(&sB[0][rn][k0 + 2 * tg + 8]);
                bl[ni][0] = LDU(&sB[1][rn][k0 + 2 * tg]);
                bl[ni][1] = LDU(&sB[1][rn][k0 + 2 * tg + 8]);
            }
#pragma unroll
            for (int mi = 0; mi < 2; mi++)
#pragma unroll
                for (int ni = 0; ni < 4; ni++) {
                    MMA_BF16(acc[mi][ni], ah[mi], bh[ni]);
                    MMA_BF16(acc[mi][ni], ah[mi], bl[ni]);
                    MMA_BF16(acc[mi][ni], al[mi], bh[ni]);
                }
        }
    }

    const bool hasb = (jb.flags & 8), rl = (jb.flags & 1);
#pragma unroll
    for (int mi = 0; mi < 2; mi++) {
#pragma unroll
        for (int ni = 0; ni < 4; ni++) {
            int r0 = m0 + wm + mi * 16 + g;
            int r1 = r0 + 8;
            int cb = n0 + wn + ni * 8 + 2 * tg;
            float v0 = acc[mi][ni][0], v1 = acc[mi][ni][1];
            float v2 = acc[mi][ni][2], v3 = acc[mi][ni][3];
            if (hasb) {
                float b0 = jb.bias[cb], b1 = jb.bias[cb + 1];
                v0 += b0; v1 += b1; v2 += b0; v3 += b1;
            }
            if (rl) {
                v0 = fmaxf(v0, 0.f); v1 = fmaxf(v1, 0.f);
                v2 = fmaxf(v2, 0.f); v3 = fmaxf(v3, 0.f);
            }
            if (jb.flags & 2) {
                *(float2*)(jb.C + (size_t)r0 * jb.N + cb) = make_float2(v0, v1);
                *(float2*)(jb.C + (size_t)r1 * jb.N + cb) = make_float2(v2, v3);
            }
            if (jb.flags & 4) {
                __nv_bfloat162 h0, l0, h1, l1;
                h0.x = __float2bfloat16(v0); h0.y = __float2bfloat16(v1);
                l0.x = __float2bfloat16(v0 - __bfloat162float(h0.x));
                l0.y = __float2bfloat16(v1 - __bfloat162float(h0.y));
                h1.x = __float2bfloat16(v2); h1.y = __float2bfloat16(v3);
                l1.x = __float2bfloat16(v2 - __bfloat162float(h1.x));
                l1.y = __float2bfloat16(v3 - __bfloat162float(h1.y));
                *(__nv_bfloat162*)(jb.Ch + (size_t)r0 * jb.N + cb) = h0;
                *(__nv_bfloat162*)(jb.Cl + (size_t)r0 * jb.N + cb) = l0;
                *(__nv_bfloat162*)(jb.Ch + (size_t)r1 * jb.N + cb) = h1;
                *(__nv_bfloat162*)(jb.Cl + (size_t)r1 * jb.N + cb) = l1;
            }
        }
    }
}

// ---------------------------------------------------------------- per-head suffix row-sum of H: hs[b,h,:] = sum_{k>=kcut_h} H[b,k,:]
__global__ __launch_bounds__(1024)
void hsum_kernel(const float* __restrict__ H, const float* __restrict__ td, int l,
                 float* __restrict__ hs) {
    int b = blockIdx.x, dc = blockIdx.y;       // 8 chunks of 32 cols
    int lane = threadIdx.x & 31;
    int kg = threadIdx.x >> 5;                 // 0..31
    int d = dc * 32 + lane;
    int kcut[HH];
#pragma unroll
    for (int h = 0; h < HH; h++) kcut[h] = compute_kcut(td[l * HH + h]);
    float acc[HH];
#pragma unroll
    for (int h = 0; h < HH; h++) acc[h] = 0.f;
    for (int k = kg; k < SEQL; k += 32) {
        float v = H[((long)b * SEQL + k) * DD + d];
#pragma unroll
        for (int h = 0; h < HH; h++)
            if (k >= kcut[h]) acc[h] += v;
    }
    __shared__ float sm[32][33];
    for (int h = 0; h < HH; h++) {
        sm[kg][lane] = acc[h];
        __syncthreads();
        if (kg == 0) {
            float t = 0.f;
#pragma unroll
            for (int i = 0; i < 32; i++) t += sm[i][lane];
            hs[((long)b * HH + h) * DD + d] = t;
        }
        __syncthreads();
    }
}

// ---------------------------------------------------------------- tailV[b,h,d] = hs[b,h,:]·vW[h*32+d,:] + (SEQ-kcut)*vb
__global__ void tailmv_kernel(const float* __restrict__ hs, const float* __restrict__ vW,
                              const float* __restrict__ vb, const float* __restrict__ td,
                              int l, float* __restrict__ tailV) {
    int bh = blockIdx.x;
    int b = bh / HH, h = bh % HH;
    int d = threadIdx.x;   // 0..31
    int kcut = compute_kcut(td[l * HH + h]);
    int n = h * DKK + d;
    const float* w = vW + (long)l * DD * DD + (long)n * DD;
    const float* s = hs + ((long)b * HH + h) * DD;
    float acc = 0.f;
#pragma unroll 4
    for (int j = 0; j < DD; j++) acc = fmaf(s[j], w[j], acc);
    tailV[bh * DKK + d] = acc + (float)(SEQL - kcut) * vb[l * DD + n];
}

// ---------------------------------------------------------------- attention (emits bf16 hi/lo ctx)
__global__ __launch_bounds__(128)
void attn_kernel(const float* __restrict__ Q, const float* __restrict__ Km,
                 const float* __restrict__ Vm, const float* __restrict__ td,
                 const float* __restrict__ scale, const float* __restrict__ tailV,
                 __nv_bfloat16* __restrict__ Ch, __nv_bfloat16* __restrict__ Cl, int l) {
    __shared__ float Ks[128][DKK];
    __shared__ float Vs[128][DKK];
    __shared__ float dec[128];
    int bh = blockIdx.y;
    int b = bh / HH, h = bh % HH;
    int tid = threadIdx.x;
    int q = blockIdx.x * 128 + tid;
    float tdh = td[l * HH + h];
    int kcut = compute_kcut(tdh);
    float c = scale[l] * rsqrtf((float)DKK);
    float4 qv[8];
    {
        const float4* qp = (const float4*)(Q + ((long)(b * SEQL + q)) * DD + h * DKK);
#pragma unroll
        for (int j = 0; j < 8; ++j) {
            float4 t = qp[j];
            t.x *= c; t.y *= c; t.z *= c; t.w *= c;
            qv[j] = t;
        }
    }
    float Z = 0.f;
    float4 cx[8];
#pragma unroll
    for (int j = 0; j < 8; ++j) cx[j] = make_float4(0.f, 0.f, 0.f, 0.f);

    for (int kb = 0; kb < kcut; kb += 128) {
        int kn = min(128, kcut - kb);
        __syncthreads();
        const float4* Kg = (const float4*)(Km + ((long)(b * SEQL + kb)) * DD + h * DKK);
        const float4* Vg = (const float4*)(Vm + ((long)(b * SEQL + kb)) * DD + h * DKK);
#pragma unroll
        for (int i = 0; i < 8; i++) {
            int idx = i * 128 + tid;
            int r = idx >> 3, c4 = idx & 7;
            if (r < kn) {
                ((float4*)Ks[r])[c4] = Kg[(long)r * (DD / 4) + c4];
                ((float4*)Vs[r])[c4] = Vg[(long)r * (DD / 4) + c4];
            }
        }
        if (tid < kn) dec[tid] = __expf(-tdh * (float)(kb + tid));
        __syncthreads();
        for (int kk = 0; kk < kn; ++kk) {
            const float4* kr = (const float4*)Ks[kk];
            float s0 = 0.f, s1 = 0.f, s2 = 0.f, s3 = 0.f;
#pragma unroll
            for (int j = 0; j < 8; j += 2) {
                float4 k0 = kr[j], k1 = kr[j + 1];
                s0 = fmaf(qv[j].x, k0.x, s0); s1 = fmaf(qv[j].y, k0.y, s1);
                s2 = fmaf(qv[j].z, k0.z, s2); s3 = fmaf(qv[j].w, k0.w, s3);
                s0 = fmaf(qv[j + 1].x, k1.x, s0); s1 = fmaf(qv[j + 1].y, k1.y, s1);
                s2 = fmaf(qv[j + 1].z, k1.z, s2); s3 = fmaf(qv[j + 1].w, k1.w, s3);
            }
            float s = ((s0 + s1) + (s2 + s3)) * dec[kk];
            float e = __expf(s);
            float w = e * e / (1.f + e);
            Z += e;
            const float4* vr = (const float4*)Vs[kk];
#pragma unroll
            for (int j = 0; j < 8; ++j) {
                float4 vv = vr[j];
                cx[j].x = fmaf(w, vv.x, cx[j].x);
                cx[j].y = fmaf(w, vv.y, cx[j].y);
                cx[j].z = fmaf(w, vv.z, cx[j].z);
                cx[j].w = fmaf(w, vv.w, cx[j].w);
            }
        }
    }
    Z += (float)(SEQL - kcut);
    float invZ = 1.f / Z;
    const float4* tv = (const float4*)(tailV + bh * DKK);
    size_t ob = ((size_t)(b * SEQL + q)) * DD + h * DKK;
#pragma unroll
    for (int j = 0; j < 8; ++j) {
        float4 t = tv[j];
        float ov[4];
        ov[0] = (cx[j].x + 0.5f * t.x) * invZ;
        ov[1] = (cx[j].y + 0.5f * t.y) * invZ;
        ov[2] = (cx[j].z + 0.5f * t.z) * invZ;
        ov[3] = (cx[j].w + 0.5f * t.w) * invZ;
#pragma unroll
        for (int u = 0; u < 4; ++u) {
            __nv_bfloat16 hh = __float2bfloat16(ov[u]);
            Ch[ob + j * 4 + u] = hh;
            Cl[ob + j * 4 + u] = __float2bfloat16(ov[u] - __bfloat162float(hh));
        }
    }
}

// ---------------------------------------------------------------- single-query attention (layer 2 last token)
__global__ __launch_bounds__(128)
void attn1_kernel(const float* __restrict__ q2, const float* __restrict__ Km,
                  const float* __restrict__ Vm, const float* __restrict__ td,
                  const float* __restrict__ scale, const float* __restrict__ tailV,
                  float* __restrict__ ctx2, int l) {
    int b = blockIdx.x / HH, h = blockIdx.x % HH;
    int tid = threadIdx.x;
    float tdh = td[l * HH + h];
    int kcut = compute_kcut(tdh);
    float c = scale[l] * rsqrtf((float)DKK);
    __shared__ float qs[DKK];
    __shared__ float ws[128];
    __shared__ float red[4];
    if (tid < DKK) qs[tid] = q2[b * DD + h * DKK + tid] * c;
    __syncthreads();
    float Zp = 0.f;
    float cxd = 0.f;
    for (int kb = 0; kb < kcut; kb += 128) {
        int kn = min(128, kcut - kb);
        float w = 0.f;
        if (tid < kn) {
            int k = kb + tid;
            const float* kr = Km + ((long)(b * SEQL + k)) * DD + h * DKK;
            float s = 0.f;
#pragma unroll
            for (int d = 0; d < DKK; ++d) s = fmaf(qs[d], kr[d], s);
            s *= __expf(-tdh * (float)k);
            float e = __expf(s);
            w = e * e / (1.f + e);
            Zp += e;
        }
        __syncthreads();
        ws[tid] = w;
        __syncthreads();
        if (tid < DKK) {
            for (int kk = 0; kk < kn; ++kk)
                cxd = fmaf(ws[kk], Vm[((long)(b * SEQL + kb + kk)) * DD + h * DKK + tid], cxd);
        }
        __syncthreads();
    }
    float s = Zp;
#pragma unroll
    for (int o = 16; o; o >>= 1) s += __shfl_xor_sync(0xffffffffu, s, o);
    if ((tid & 31) == 0) red[tid >> 5] = s;
    __syncthreads();
    float Z = red[0] + red[1] + red[2] + red[3] + (float)(SEQL - kcut);
    if (tid < DKK)
        ctx2[b * DD + h * DKK + tid] = (cxd + 0.5f * tailV[blockIdx.x * DKK + tid]) / Z;
}

// ---------------------------------------------------------------- small-M GEMM (M=2 rows), fp32
template <bool RELU>
__global__ void rowgemm_kernel(const float* __restrict__ A, long lda,
                               const float* __restrict__ W, const float* __restrict__ bias,
                               float* __restrict__ C, int K, int N) {
    extern __shared__ float arow[];
    int m = blockIdx.x;
    int n = blockIdx.y * blockDim.x + threadIdx.x;
    for (int i = threadIdx.x; i < K; i += blockDim.x) arow[i] = A[(long)m * lda + i];
    __syncthreads();
    float s = bias[n];
    const float* wr = W + (long)n * K;
#pragma unroll 4
    for (int kk = 0; kk < K; ++kk) s = fmaf(arow[kk], wr[kk], s);
    if (RELU) s = fmaxf(s, 0.f);
    C[(long)m * N + n] = s;
}

// ---------------------------------------------------------------- residual + layernorm; optional 2nd partial + bf16 emit
template <bool TWO, bool EMIT>
__global__ void ln_kernel(const float* __restrict__ z, long zs,
                          const float* __restrict__ z2,
                          const float* __restrict__ res, long rs,
                          const float* __restrict__ g, const float* __restrict__ be,
                          float* __restrict__ out, long os,
                          __nv_bfloat16* __restrict__ oh, __nv_bfloat16* __restrict__ ol) {
    int m = blockIdx.x, t = threadIdx.x;
    float v = z[(long)m * zs + t] + res[(long)m * rs + t];
    if (TWO) v += z2[(long)m * zs + t];
    __shared__ float sm[8];
    float s = v;
#pragma unroll
    for (int o = 16; o; o >>= 1) s += __shfl_xor_sync(0xffffffffu, s, o);
    if ((t & 31) == 0) sm[t >> 5] = s;
    __syncthreads();
    float tot = 0.f;
#pragma unroll
    for (int i = 0; i < 8; i++) tot += sm[i];
    float mean = tot * (1.0f / DD);
    float dv = v - mean;
    float s2 = dv * dv;
    __syncthreads();
#pragma unroll
    for (int o = 16; o; o >>= 1) s2 += __shfl_xor_sync(0xffffffffu, s2, o);
    if ((t & 31) == 0) sm[t >> 5] = s2;
    __syncthreads();
    float var = 0.f;
#pragma unroll
    for (int i = 0; i < 8; i++) var += sm[i];
    var *= (1.0f / DD);
    float o = dv * rsqrtf(var + EPSF) * g[t] + be[t];
    out[(long)m * os + t] = o;
    if (EMIT) {
        __nv_bfloat16 hh = __float2bfloat16(o);
        oh[(long)m * DD + t] = hh;
        ol[(long)m * DD + t] = __float2bfloat16(o - __bfloat162float(hh));
    }
}

// ---------------------------------------------------------------- final projection
__global__ void out_kernel(const float* __restrict__ r2, const float* __restrict__ ow,
                           const float* __restrict__ ob, float* __restrict__ out) {
    int b = blockIdx.x, t = threadIdx.x;
    float p = r2[b * DD + t] * ow[t];
    __shared__ float sm[8];
    float s = p;
#pragma unroll
    for (int o = 16; o; o >>= 1) s += __shfl_xor_sync(0xffffffffu, s, o);
    if ((t & 31) == 0) sm[t >> 5] = s;
    __syncthreads();
    if (t == 0) {
        float tot = 0.f;
#pragma unroll
        for (int i = 0; i < 8; i++) tot += sm[i];
        out[b] = 0.5f * tot + ob[0];
    }
}

// ================================================================ host orchestration
extern "C" void kernel_launch(void* const* d_in, const int* in_sizes, int n_in,
                              void* d_out, int out_size) {
    const float* x   = (const float*)d_in[0];
    const float* cw  = (const float*)d_in[1];
    const float* cb  = (const float*)d_in[2];
    const float* bg  = (const float*)d_in[3];
    const float* bbn = (const float*)d_in[4];
    const float* pe  = (const float*)d_in[5];
    const float* qW  = (const float*)d_in[6];
    const float* qb  = (const float*)d_in[7];
    const float* kW  = (const float*)d_in[8];
    const float* kb  = (const float*)d_in[9];
    const float* vW  = (const float*)d_in[10];
    const float* vb  = (const float*)d_in[11];
    const float* oW  = (const float*)d_in[12];
    const float* ob  = (const float*)d_in[13];
    const float* scale = (const float*)d_in[14];
    const float* td  = (const float*)d_in[15];
    const float* ln1g = (const float*)d_in[16];
    const float* ln1b = (const float*)d_in[17];
    const float* f1W = (const float*)d_in[18];
    const float* f1b = (const float*)d_in[19];
    const float* f2W = (const float*)d_in[20];
    const float* f2b = (const float*)d_in[21];
    const float* ln2g = (const float*)d_in[22];
    const float* ln2b = (const float*)d_in[23];
    const float* outW = (const float*)d_in[24];
    const float* outb = (const float*)d_in[25];
    float* out = (float*)d_out;

    float* buf = nullptr;
    cudaGetSymbolAddress((void**)&buf, g_buf);
    float* H0 = buf;
    float* H2 = buf + 1L * NH;
    float* Qb = buf + 2L * NH;
    float* Kb = buf + 3L * NH;
    float* Vb = buf + 4L * NH;
    float* T  = buf + 5L * NH;
    float* TP = buf + 6L * NH;
    __nv_bfloat16* B16 = (__nv_bfloat16*)(buf + 7L * NH);
    __nv_bfloat16* H0h = B16;
    __nv_bfloat16* H0l = B16 + 1L * NH;
    __nv_bfloat16* H2h = B16 + 2L * NH;
    __nv_bfloat16* H2l = B16 + 3L * NH;
    __nv_bfloat16* CXh = B16 + 4L * NH;
    __nv_bfloat16* CXl = B16 + 5L * NH;
    __nv_bfloat16* FFh = B16 + 6L * NH;
    __nv_bfloat16* FFl = B16 + 6L * NH + NFF;
    __nv_bfloat16* Wb  = B16 + 6L * NH + 2L * NFF;
    float* TAIL = buf + 7L * NH + BF16_FLOATS;
    float* SMALL = TAIL + 512;
    float* Q2 = SMALL, *CTX2 = SMALL + 512, *T2 = SMALL + 1024, *R1 = SMALL + 1536;
    float* FFROW = SMALL + 2048, *T3 = SMALL + 4096, *R2 = SMALL + 4608;
    float* HS = SMALL + 5632;   // [BB][HH][DD] = 4096 floats

    auto WQH = [&](int l){ return Wb + 0       + l * 65536; };
    auto WQL = [&](int l){ return Wb + 131072  + l * 65536; };
    auto WKH = [&](int l){ return Wb + 262144  + l * 65536; };
    auto WKL = [&](int l){ return Wb + 393216  + l * 65536; };
    auto WVH = [&](int l){ return Wb + 524288  + l * 65536; };
    auto WVL = [&](int l){ return Wb + 655360  + l * 65536; };
    auto WOH = [&](int l){ return Wb + 786432  + l * 65536; };
    auto WOL = [&](int l){ return Wb + 917504  + l * 65536; };
    auto WF1H = [&](int l){ return Wb + 1048576 + l * 262144; };
    auto WF1L = [&](int l){ return Wb + 1572864 + l * 262144; };
    auto WF2H = [&](int l){ return Wb + 2097152 + l * 262144; };
    auto WF2L = [&](int l){ return Wb + 2621440 + l * 262144; };

    const int M = BB * SEQL;                 // 4096
    dim3 gAttn(SEQL / 128, BB * HH);
    dim3 gHsum(BB, 8);

    // --- stem + weight split ---
    conv_pe_kernel<<<(NH + 255) / 256, 256>>>(x, cw, cb, bg, bbn, pe, H0, H0h, H0l);
    wsplit_kernel<<<dim3(128, 1, 6), 256>>>(qW, kW, vW, oW, f1W, f2W, Wb);

    // --- layer 0 ---
    {   // Q full; K,V only head rows (early-exit via tdl)
        TcJobs3 J{};
        J.j[0] = {H0h, H0l, WQH(0), WQL(0), qb, Qb, nullptr, nullptr, nullptr, DD, DD, DD, DD, 2 | 8};
        J.j[1] = {H0h, H0l, WKH(0), WKL(0), kb, Kb, nullptr, nullptr, td,      DD, DD, DD, DD, 2 | 8};
        J.j[2] = {H0h, H0l, WVH(0), WVL(0), vb, Vb, nullptr, nullptr, td,      DD, DD, DD, DD, 2 | 8};
        tc_kernel<<<dim3(DD / 64, M / 128, 3), 256>>>(J);
    }
    hsum_kernel<<<gHsum, 1024>>>(H0, td, 0, HS);
    tailmv_kernel<<<BB * HH, DKK>>>(HS, vW, vb, td, 0, TAIL);
    attn_kernel<<<gAttn, 128>>>(Qb, Kb, Vb, td, scale, TAIL, CXh, CXl, 0);
    {
        TcJobs3 J{};
        J.j[0] = {CXh, CXl, WOH(0), WOL(0), ob, T, nullptr, nullptr, nullptr, DD, DD, DD, DD, 2 | 8};
        tc_kernel<<<dim3(DD / 64, M / 128, 1), 256>>>(J);
    }
    ln_kernel<false, true><<<M, 256>>>(T, DD, nullptr, H0, DD, ln1g, ln1b, H2, DD, H2h, H2l);
    {
        TcJobs3 J{};
        J.j[0] = {H2h, H2l, WF1H(0), WF1L(0), f1b, nullptr, FFh, FFl, nullptr, DD, DD, DFFN, DD, 1 | 4 | 8};
        tc_kernel<<<dim3(DFFN / 64, M / 128, 1), 256>>>(J);
    }
    {   // FFN2 split-K=2; partials T (+bias) and TP
        TcJobs3 J{};
        J.j[0] = {FFh,       FFl,       WF2H(0),       WF2L(0),       f2b, T,  nullptr, nullptr, nullptr, DFFN, DFFN, DD, 512, 2 | 8};
        J.j[1] = {FFh + 512, FFl + 512, WF2H(0) + 512, WF2L(0) + 512, f2b, TP, nullptr, nullptr, nullptr, DFFN, DFFN, DD, 512, 2};
        tc_kernel<<<dim3(DD / 64, M / 128, 2), 256>>>(J);
    }
    ln_kernel<true, true><<<M, 256>>>(T, DD, TP, H2, DD, ln2g, ln2b, H0, DD, H0h, H0l);

    // --- layer 1 (only last token needed downstream of attention) ---
    const float* qW1 = qW + DD * DD;   const float* qb1 = qb + DD;
    const float* oW1 = oW + DD * DD;   const float* ob1 = ob + DD;
    const float* kb1 = kb + DD;        const float* vb1 = vb + DD;
    const float* ln1g1 = ln1g + DD;    const float* ln1b1 = ln1b + DD;
    const float* ln2g1 = ln2g + DD;    const float* ln2b1 = ln2b + DD;
    const float* f1W1 = f1W + DFFN * DD; const float* f1b1 = f1b + DFFN;
    const float* f2W1 = f2W + DD * DFFN; const float* f2b1 = f2b + DD;
    const float* hlast = H0 + (long)(SEQL - 1) * DD;

    {   // K,V head rows only (early-exit)
        TcJobs3 J{};
        J.j[0] = {H0h, H0l, WKH(1), WKL(1), kb1, Kb, nullptr, nullptr, td + HH, DD, DD, DD, DD, 2 | 8};
        J.j[1] = {H0h, H0l, WVH(1), WVL(1), vb1, Vb, nullptr, nullptr, td + HH, DD, DD, DD, DD, 2 | 8};
        tc_kernel<<<dim3(DD / 64, M / 128, 2), 256>>>(J);
    }
    hsum_kernel<<<gHsum, 1024>>>(H0, td, 1, HS);
    tailmv_kernel<<<BB * HH, DKK>>>(HS, vW, vb, td, 1, TAIL);

    rowgemm_kernel<false><<<dim3(BB, 1), 256, DD * 4>>>(hlast, (long)SEQL * DD, qW1, qb1, Q2, DD, DD);
    attn1_kernel<<<BB * HH, 128>>>(Q2, Kb, Vb, td, scale, TAIL, CTX2, 1);
    rowgemm_kernel<false><<<dim3(BB, 1), 256, DD * 4>>>(CTX2, DD, oW1, ob1, T2, DD, DD);
    ln_kernel<false, false><<<BB, 256>>>(T2, DD, nullptr, hlast, (long)SEQL * DD, ln1g1, ln1b1, R1, DD, nullptr, nullptr);
    rowgemm_kernel<true ><<<dim3(BB, DFFN / 256), 256, DD * 4>>>(R1, DD, f1W1, f1b1, FFROW, DD, DFFN);
    rowgemm_kernel<false><<<dim3(BB, 1), 256, DFFN * 4>>>(FFROW, DFFN, f2W1, f2b1, T3, DFFN, DD);
    ln_kernel<false, false><<<BB, 256>>>(T3, DD, nullptr, R1, DD, ln2g1, ln2b1, R2, DD, nullptr, nullptr);

    out_kernel<<<BB, 256>>>(R2, outW, outb, out);
}

// round 8
// speedup vs baseline: 1.6923x; 1.6923x over previous
#include <cuda_runtime.h>
#include <cuda_bf16.h>

#define BB 2
#define SEQL 2048
#define DD 256
#define HH 8
#define DKK 32
#define DFFN 1024
#define EPSF 1e-5f

#define NH  (BB*SEQL*DD)      /* 1048576 */
#define NFF (BB*SEQL*DFFN)    /* 4194304 */

#define BF16_FLOATS 8912896L
__device__ float g_buf[7L*NH + BF16_FLOATS + 512 + 32768];

__device__ __forceinline__ int compute_kcut(float tdh) {
    if (!(tdh > 1e-6f)) return SEQL;
    float c = 33.0f / tdh;     // exp(s * e^-33) == 1.0f exactly for |s| < 1e7
    if (c >= (float)SEQL) return SEQL;
    int k = (int)ceilf(c);
    return k < SEQL ? k : SEQL;
}

// ---------------------------------------------------------------- conv + bn + relu + pe (+ bf16 split)
__global__ void conv_pe_kernel(const float* __restrict__ x, const float* __restrict__ cw,
                               const float* __restrict__ cb, const float* __restrict__ bg,
                               const float* __restrict__ bb, const float* __restrict__ pe,
                               float* __restrict__ out,
                               __nv_bfloat16* __restrict__ oh, __nv_bfloat16* __restrict__ ol) {
    int idx = blockIdx.x * 256 + threadIdx.x;
    if (idx >= NH) return;
    int d = idx & (DD - 1);
    int t = (idx >> 8) & (SEQL - 1);
    int b = idx >> 19;
    const float* xb = x + b * SEQL;
    float xm = t > 0 ? xb[t - 1] : 0.f;
    float x0 = xb[t];
    float xp = (t < SEQL - 1) ? xb[t + 1] : 0.f;
    float v = cw[d * 3 + 0] * xm + cw[d * 3 + 1] * x0 + cw[d * 3 + 2] * xp + cb[d];
    v = v * rsqrtf(1.f + EPSF) * bg[d] + bb[d];
    v = fmaxf(v, 0.f);
    float r = v + pe[t * DD + d];
    out[idx] = r;
    __nv_bfloat16 h = __float2bfloat16(r);
    oh[idx] = h;
    ol[idx] = __float2bfloat16(r - __bfloat162float(h));
}

// ---------------------------------------------------------------- weight split fp32 -> bf16 hi/lo
__global__ void wsplit_kernel(const float* __restrict__ q, const float* __restrict__ k,
                              const float* __restrict__ v, const float* __restrict__ o,
                              const float* __restrict__ f1, const float* __restrict__ f2,
                              __nv_bfloat16* __restrict__ W) {
    int z = blockIdx.z;
    const float* src; long n; long off;
    switch (z) {
        case 0: src = q;  n = 131072; off = 0;       break;
        case 1: src = k;  n = 131072; off = 262144;  break;
        case 2: src = v;  n = 131072; off = 524288;  break;
        case 3: src = o;  n = 131072; off = 786432;  break;
        case 4: src = f1; n = 524288; off = 1048576; break;
        default: src = f2; n = 524288; off = 2097152; break;
    }
    __nv_bfloat16* dh = W + off;
    __nv_bfloat16* dl = dh + n;
    for (long i = blockIdx.x * 256L + threadIdx.x; i < n; i += (long)gridDim.x * 256L) {
        float xx = src[i];
        __nv_bfloat16 h = __float2bfloat16(xx);
        dh[i] = h;
        dl[i] = __float2bfloat16(xx - __bfloat162float(h));
    }
}

// ---------------------------------------------------------------- HMMA GEMM: C[M,N] = A[M,K] @ W[N,K]^T
struct TcJob {
    const __nv_bfloat16 *Ah, *Al;
    const __nv_bfloat16 *Wh, *Wl;
    const float* bias;
    float* C;
    __nv_bfloat16 *Ch, *Cl;
    const float* tdl;            // if set: CTA exits when (m0 & (SEQL-1)) >= max kcut
    int lda, ldw, N, K, flags;   // flags: 1=RELU 2=FP32OUT 4=BF16OUT 8=BIAS
};
struct TcJobs3 { TcJob j[3]; };

#define MMA_BF16(c, a, b) \
    asm volatile("mma.sync.aligned.m16n8k16.row.col.f32.bf16.bf16.f32 " \
        "{%0,%1,%2,%3}, {%4,%5,%6,%7}, {%8,%9}, {%0,%1,%2,%3};" \
        : "+f"((c)[0]), "+f"((c)[1]), "+f"((c)[2]), "+f"((c)[3]) \
        : "r"((a)[0]), "r"((a)[1]), "r"((a)[2]), "r"((a)[3]), "r"((b)[0]), "r"((b)[1]))

#define LDU(p) (*(const unsigned*)(p))

__global__ __launch_bounds__(256) void tc_kernel(TcJobs3 jobs) {
    TcJob jb = jobs.j[blockIdx.z];
    const int m0 = blockIdx.y * 128, n0 = blockIdx.x * 64;
    if (jb.tdl) {
        int kmax = 0;
#pragma unroll
        for (int h = 0; h < HH; h++) {
            int kc = compute_kcut(jb.tdl[h]);
            kmax = kc > kmax ? kc : kmax;
        }
        if ((m0 & (SEQL - 1)) >= kmax) return;   // rows unused downstream
    }
    __shared__ __nv_bfloat16 sA[2][128][40];   // [hi/lo][row][k+pad]
    __shared__ __nv_bfloat16 sB[2][64][40];
    const int tid = threadIdx.x, wid = tid >> 5, lane = tid & 31;
    const int wm = (wid & 3) * 32, wn = (wid >> 2) * 32;
    const int g = lane >> 2, tg = lane & 3;

    float acc[2][4][4];
#pragma unroll
    for (int mi = 0; mi < 2; mi++)
#pragma unroll
        for (int ni = 0; ni < 4; ni++)
#pragma unroll
            for (int r = 0; r < 4; r++) acc[mi][ni][r] = 0.f;

    const int brow = tid >> 2, bc8 = tid & 3;

    for (int kb = 0; kb < jb.K; kb += 32) {
        // ---- global -> regs (A: 128x32 hi+lo; B: 64x32 hi+lo) ----
        uint4 ra_h[2], ra_l[2], rb_h, rb_l;
#pragma unroll
        for (int i = 0; i < 2; i++) {
            int idx = i * 256 + tid;             // 512 uint4 over A tile
            int rr = idx >> 2, cc = idx & 3;
            size_t go = (size_t)(m0 + rr) * jb.lda + kb + cc * 8;
            ra_h[i] = *(const uint4*)(jb.Ah + go);
            ra_l[i] = *(const uint4*)(jb.Al + go);
        }
        {
            size_t go = (size_t)(n0 + brow) * jb.ldw + kb + bc8 * 8;
            rb_h = *(const uint4*)(jb.Wh + go);
            rb_l = *(const uint4*)(jb.Wl + go);
        }
        __syncthreads();
#pragma unroll
        for (int i = 0; i < 2; i++) {
            int idx = i * 256 + tid;
            int rr = idx >> 2, cc = idx & 3;
            *(uint4*)&sA[0][rr][cc * 8] = ra_h[i];
            *(uint4*)&sA[1][rr][cc * 8] = ra_l[i];
        }
        *(uint4*)&sB[0][brow][bc8 * 8] = rb_h;
        *(uint4*)&sB[1][brow][bc8 * 8] = rb_l;
        __syncthreads();

        // ---- compute: 2 k16 steps ----
#pragma unroll
        for (int ks = 0; ks < 2; ks++) {
            const int k0 = ks * 16;
            unsigned ah[2][4], al[2][4];
#pragma unroll
            for (int mi = 0; mi < 2; mi++) {
                int r = wm + mi * 16 + g;
                ah[mi][0] = LDU(&sA[0][r][k0 + 2 * tg]);
                ah[mi][1] = LDU(&sA[0][r + 8][k0 + 2 * tg]);
                ah[mi][2] = LDU(&sA[0][r][k0 + 2 * tg + 8]);
                ah[mi][3] = LDU(&sA[0][r + 8][k0 + 2 * tg + 8]);
                al[mi][0] = LDU(&sA[1][r][k0 + 2 * tg]);
                al[mi][1] = LDU(&sA[1][r + 8][k0 + 2 * tg]);
                al[mi][2] = LDU(&sA[1][r][k0 + 2 * tg + 8]);
                al[mi][3] = LDU(&sA[1][r + 8][k0 + 2 * tg + 8]);
            }
            unsigned bh[4][2], bl[4][2];
#pragma unroll
            for (int ni = 0; ni < 4; ni++) {
                int rn = wn + ni * 8 + g;
                bh[ni][0] = LDU(&sB[0][rn][k0 + 2 * tg]);
                bh[ni][1] = LDU(&sB[0][rn][k0 + 2 * tg + 8]);
                bl[ni][0] = LDU(&sB[1][rn][k0 + 2 * tg]);
                bl[ni][1] = LDU(&sB[1][rn][k0 + 2 * tg + 8]);
            }
#pragma unroll
            for (int mi = 0; mi < 2; mi++)
#pragma unroll
                for (int ni = 0; ni < 4; ni++) {
                    MMA_BF16(acc[mi][ni], ah[mi], bh[ni]);
                    MMA_BF16(acc[mi][ni], ah[mi], bl[ni]);
                    MMA_BF16(acc[mi][ni], al[mi], bh[ni]);
                }
        }
    }

    const bool hasb = (jb.flags & 8), rl = (jb.flags & 1);
#pragma unroll
    for (int mi = 0; mi < 2; mi++) {
#pragma unroll
        for (int ni = 0; ni < 4; ni++) {
            int r0 = m0 + wm + mi * 16 + g;
            int r1 = r0 + 8;
            int cb = n0 + wn + ni * 8 + 2 * tg;
            float v0 = acc[mi][ni][0], v1 = acc[mi][ni][1];
            float v2 = acc[mi][ni][2], v3 = acc[mi][ni][3];
            if (hasb) {
                float b0 = jb.bias[cb], b1 = jb.bias[cb + 1];
                v0 += b0; v1 += b1; v2 += b0; v3 += b1;
            }
            if (rl) {
                v0 = fmaxf(v0, 0.f); v1 = fmaxf(v1, 0.f);
                v2 = fmaxf(v2, 0.f); v3 = fmaxf(v3, 0.f);
            }
            if (jb.flags & 2) {
                *(float2*)(jb.C + (size_t)r0 * jb.N + cb) = make_float2(v0, v1);
                *(float2*)(jb.C + (size_t)r1 * jb.N + cb) = make_float2(v2, v3);
            }
            if (jb.flags & 4) {
                __nv_bfloat162 h0, l0, h1, l1;
                h0.x = __float2bfloat16(v0); h0.y = __float2bfloat16(v1);
                l0.x = __float2bfloat16(v0 - __bfloat162float(h0.x));
                l0.y = __float2bfloat16(v1 - __bfloat162float(h0.y));
                h1.x = __float2bfloat16(v2); h1.y = __float2bfloat16(v3);
                l1.x = __float2bfloat16(v2 - __bfloat162float(h1.x));
                l1.y = __float2bfloat16(v3 - __bfloat162float(h1.y));
                *(__nv_bfloat162*)(jb.Ch + (size_t)r0 * jb.N + cb) = h0;
                *(__nv_bfloat162*)(jb.Cl + (size_t)r0 * jb.N + cb) = l0;
                *(__nv_bfloat162*)(jb.Ch + (size_t)r1 * jb.N + cb) = h1;
                *(__nv_bfloat162*)(jb.Cl + (size_t)r1 * jb.N + cb) = l1;
            }
        }
    }
}

// ---------------------------------------------------------------- chunk sums of H: CS[b][c][d] = sum_{r=0..63} H[b, c*64+r, d]
__global__ __launch_bounds__(256)
void csum_kernel(const float* __restrict__ H, float* __restrict__ CS) {
    int b = blockIdx.x, c = blockIdx.y;
    int d = threadIdx.x;
    const float* p = H + ((long)b * SEQL + c * 64) * DD + d;
    float s0 = 0.f, s1 = 0.f, s2 = 0.f, s3 = 0.f;
#pragma unroll
    for (int r = 0; r < 64; r += 4) {
        s0 += p[(long)(r    ) * DD];
        s1 += p[(long)(r + 1) * DD];
        s2 += p[(long)(r + 2) * DD];
        s3 += p[(long)(r + 3) * DD];
    }
    CS[((long)b * 32 + c) * DD + d] = (s0 + s1) + (s2 + s3);
}

// ---------------------------------------------------------------- tailV[b,h,d] from chunk sums + boundary rows, fused matvec vs vW
__global__ __launch_bounds__(256)
void tailmv2_kernel(const float* __restrict__ H, const float* __restrict__ CS,
                    const float* __restrict__ vW, const float* __restrict__ vb,
                    const float* __restrict__ td, int l, float* __restrict__ tailV) {
    __shared__ float sfx[DD];
    __shared__ float red[DKK][8];
    int bh = blockIdx.x;
    int b = bh / HH, h = bh % HH;
    int tid = threadIdx.x;
    int kcut = compute_kcut(td[l * HH + h]);
    int cb = kcut >> 6;
    int cend = (cb + 1) << 6; if (cend > SEQL) cend = SEQL;
    // suffix sum for column d = tid
    float s = 0.f;
    for (int k = kcut; k < cend; ++k) s += H[((long)b * SEQL + k) * DD + tid];
    for (int c = cb + 1; c < 32; ++c) s += CS[((long)b * 32 + c) * DD + tid];
    sfx[tid] = s;
    __syncthreads();
    // matvec: tail[dl] = sfx . vW[l, h*32+dl, :]
    int dl = tid & 31, grp = tid >> 5;
    int n = h * DKK + dl;
    const float* w = vW + (long)l * DD * DD + (long)n * DD + grp * 32;
    const float* sv = sfx + grp * 32;
    float p = 0.f;
#pragma unroll
    for (int j = 0; j < 32; ++j) p = fmaf(sv[j], w[j], p);
    red[dl][grp] = p;
    __syncthreads();
    if (tid < DKK) {
        float t = 0.f;
#pragma unroll
        for (int gi = 0; gi < 8; gi++) t += red[tid][gi];
        tailV[bh * DKK + tid] = t + (float)(SEQL - kcut) * vb[l * DD + h * DKK + tid];
    }
}

// ---------------------------------------------------------------- attention (emits bf16 hi/lo ctx)
__global__ __launch_bounds__(128)
void attn_kernel(const float* __restrict__ Q, const float* __restrict__ Km,
                 const float* __restrict__ Vm, const float* __restrict__ td,
                 const float* __restrict__ scale, const float* __restrict__ tailV,
                 __nv_bfloat16* __restrict__ Ch, __nv_bfloat16* __restrict__ Cl, int l) {
    __shared__ float Ks[128][DKK];
    __shared__ float Vs[128][DKK];
    __shared__ float dec[128];
    int bh = blockIdx.y;
    int b = bh / HH, h = bh % HH;
    int tid = threadIdx.x;
    int q = blockIdx.x * 128 + tid;
    float tdh = td[l * HH + h];
    int kcut = compute_kcut(tdh);
    float c = scale[l] * rsqrtf((float)DKK);
    float4 qv[8];
    {
        const float4* qp = (const float4*)(Q + ((long)(b * SEQL + q)) * DD + h * DKK);
#pragma unroll
        for (int j = 0; j < 8; ++j) {
            float4 t = qp[j];
            t.x *= c; t.y *= c; t.z *= c; t.w *= c;
            qv[j] = t;
        }
    }
    float Z = 0.f;
    float4 cx[8];
#pragma unroll
    for (int j = 0; j < 8; ++j) cx[j] = make_float4(0.f, 0.f, 0.f, 0.f);

    for (int kb = 0; kb < kcut; kb += 128) {
        int kn = min(128, kcut - kb);
        __syncthreads();
        const float4* Kg = (const float4*)(Km + ((long)(b * SEQL + kb)) * DD + h * DKK);
        const float4* Vg = (const float4*)(Vm + ((long)(b * SEQL + kb)) * DD + h * DKK);
#pragma unroll
        for (int i = 0; i < 8; i++) {
            int idx = i * 128 + tid;
            int r = idx >> 3, c4 = idx & 7;
            if (r < kn) {
                ((float4*)Ks[r])[c4] = Kg[(long)r * (DD / 4) + c4];
                ((float4*)Vs[r])[c4] = Vg[(long)r * (DD / 4) + c4];
            }
        }
        if (tid < kn) dec[tid] = __expf(-tdh * (float)(kb + tid));
        __syncthreads();
        for (int kk = 0; kk < kn; ++kk) {
            const float4* kr = (const float4*)Ks[kk];
            float s0 = 0.f, s1 = 0.f, s2 = 0.f, s3 = 0.f;
#pragma unroll
            for (int j = 0; j < 8; j += 2) {
                float4 k0 = kr[j], k1 = kr[j + 1];
                s0 = fmaf(qv[j].x, k0.x, s0); s1 = fmaf(qv[j].y, k0.y, s1);
                s2 = fmaf(qv[j].z, k0.z, s2); s3 = fmaf(qv[j].w, k0.w, s3);
                s0 = fmaf(qv[j + 1].x, k1.x, s0); s1 = fmaf(qv[j + 1].y, k1.y, s1);
                s2 = fmaf(qv[j + 1].z, k1.z, s2); s3 = fmaf(qv[j + 1].w, k1.w, s3);
            }
            float s = ((s0 + s1) + (s2 + s3)) * dec[kk];
            float e = __expf(s);
            float w = e * e / (1.f + e);
            Z += e;
            const float4* vr = (const float4*)Vs[kk];
#pragma unroll
            for (int j = 0; j < 8; ++j) {
                float4 vv = vr[j];
                cx[j].x = fmaf(w, vv.x, cx[j].x);
                cx[j].y = fmaf(w, vv.y, cx[j].y);
                cx[j].z = fmaf(w, vv.z, cx[j].z);
                cx[j].w = fmaf(w, vv.w, cx[j].w);
            }
        }
    }
    Z += (float)(SEQL - kcut);
    float invZ = 1.f / Z;
    const float4* tv = (const float4*)(tailV + bh * DKK);
    size_t ob = ((size_t)(b * SEQL + q)) * DD + h * DKK;
#pragma unroll
    for (int j = 0; j < 8; ++j) {
        float4 t = tv[j];
        float ov[4];
        ov[0] = (cx[j].x + 0.5f * t.x) * invZ;
        ov[1] = (cx[j].y + 0.5f * t.y) * invZ;
        ov[2] = (cx[j].z + 0.5f * t.z) * invZ;
        ov[3] = (cx[j].w + 0.5f * t.w) * invZ;
#pragma unroll
        for (int u = 0; u < 4; ++u) {
            __nv_bfloat16 hh = __float2bfloat16(ov[u]);
            Ch[ob + j * 4 + u] = hh;
            Cl[ob + j * 4 + u] = __float2bfloat16(ov[u] - __bfloat162float(hh));
        }
    }
}

// ---------------------------------------------------------------- single-query attention (layer 2 last token)
__global__ __launch_bounds__(128)
void attn1_kernel(const float* __restrict__ q2, const float* __restrict__ Km,
                  const float* __restrict__ Vm, const float* __restrict__ td,
                  const float* __restrict__ scale, const float* __restrict__ tailV,
                  float* __restrict__ ctx2, int l) {
    int b = blockIdx.x / HH, h = blockIdx.x % HH;
    int tid = threadIdx.x;
    float tdh = td[l * HH + h];
    int kcut = compute_kcut(tdh);
    float c = scale[l] * rsqrtf((float)DKK);
    __shared__ float qs[DKK];
    __shared__ float ws[128];
    __shared__ float red[4];
    if (tid < DKK) qs[tid] = q2[b * DD + h * DKK + tid] * c;
    __syncthreads();
    float Zp = 0.f;
    float cxd = 0.f;
    for (int kb = 0; kb < kcut; kb += 128) {
        int kn = min(128, kcut - kb);
        float w = 0.f;
        if (tid < kn) {
            int k = kb + tid;
            const float* kr = Km + ((long)(b * SEQL + k)) * DD + h * DKK;
            float s = 0.f;
#pragma unroll
            for (int d = 0; d < DKK; ++d) s = fmaf(qs[d], kr[d], s);
            s *= __expf(-tdh * (float)k);
            float e = __expf(s);
            w = e * e / (1.f + e);
            Zp += e;
        }
        __syncthreads();
        ws[tid] = w;
        __syncthreads();
        if (tid < DKK) {
            for (int kk = 0; kk < kn; ++kk)
                cxd = fmaf(ws[kk], Vm[((long)(b * SEQL + kb + kk)) * DD + h * DKK + tid], cxd);
        }
        __syncthreads();
    }
    float s = Zp;
#pragma unroll
    for (int o = 16; o; o >>= 1) s += __shfl_xor_sync(0xffffffffu, s, o);
    if ((tid & 31) == 0) red[tid >> 5] = s;
    __syncthreads();
    float Z = red[0] + red[1] + red[2] + red[3] + (float)(SEQL - kcut);
    if (tid < DKK)
        ctx2[b * DD + h * DKK + tid] = (cxd + 0.5f * tailV[blockIdx.x * DKK + tid]) / Z;
}

// ---------------------------------------------------------------- small-M GEMM (M=2 rows), fp32
template <bool RELU>
__global__ void rowgemm_kernel(const float* __restrict__ A, long lda,
                               const float* __restrict__ W, const float* __restrict__ bias,
                               float* __restrict__ C, int K, int N) {
    extern __shared__ float arow[];
    int m = blockIdx.x;
    int n = blockIdx.y * blockDim.x + threadIdx.x;
    for (int i = threadIdx.x; i < K; i += blockDim.x) arow[i] = A[(long)m * lda + i];
    __syncthreads();
    float s = bias[n];
    const float* wr = W + (long)n * K;
#pragma unroll 4
    for (int kk = 0; kk < K; ++kk) s = fmaf(arow[kk], wr[kk], s);
    if (RELU) s = fmaxf(s, 0.f);
    C[(long)m * N + n] = s;
}

// ---------------------------------------------------------------- residual + layernorm; optional 2nd partial + bf16 emit
template <bool TWO, bool EMIT>
__global__ void ln_kernel(const float* __restrict__ z, long zs,
                          const float* __restrict__ z2,
                          const float* __restrict__ res, long rs,
                          const float* __restrict__ g, const float* __restrict__ be,
                          float* __restrict__ out, long os,
                          __nv_bfloat16* __restrict__ oh, __nv_bfloat16* __restrict__ ol) {
    int m = blockIdx.x, t = threadIdx.x;
    float v = z[(long)m * zs + t] + res[(long)m * rs + t];
    if (TWO) v += z2[(long)m * zs + t];
    __shared__ float sm[8];
    float s = v;
#pragma unroll
    for (int o = 16; o; o >>= 1) s += __shfl_xor_sync(0xffffffffu, s, o);
    if ((t & 31) == 0) sm[t >> 5] = s;
    __syncthreads();
    float tot = 0.f;
#pragma unroll
    for (int i = 0; i < 8; i++) tot += sm[i];
    float mean = tot * (1.0f / DD);
    float dv = v - mean;
    float s2 = dv * dv;
    __syncthreads();
#pragma unroll
    for (int o = 16; o; o >>= 1) s2 += __shfl_xor_sync(0xffffffffu, s2, o);
    if ((t & 31) == 0) sm[t >> 5] = s2;
    __syncthreads();
    float var = 0.f;
#pragma unroll
    for (int i = 0; i < 8; i++) var += sm[i];
    var *= (1.0f / DD);
    float o = dv * rsqrtf(var + EPSF) * g[t] + be[t];
    out[(long)m * os + t] = o;
    if (EMIT) {
        __nv_bfloat16 hh = __float2bfloat16(o);
        oh[(long)m * DD + t] = hh;
        ol[(long)m * DD + t] = __float2bfloat16(o - __bfloat162float(hh));
    }
}

// ---------------------------------------------------------------- final projection
__global__ void out_kernel(const float* __restrict__ r2, const float* __restrict__ ow,
                           const float* __restrict__ ob, float* __restrict__ out) {
    int b = blockIdx.x, t = threadIdx.x;
    float p = r2[b * DD + t] * ow[t];
    __shared__ float sm[8];
    float s = p;
#pragma unroll
    for (int o = 16; o; o >>= 1) s += __shfl_xor_sync(0xffffffffu, s, o);
    if ((t & 31) == 0) sm[t >> 5] = s;
    __syncthreads();
    if (t == 0) {
        float tot = 0.f;
#pragma unroll
        for (int i = 0; i < 8; i++) tot += sm[i];
        out[b] = 0.5f * tot + ob[0];
    }
}

// ================================================================ host orchestration
extern "C" void kernel_launch(void* const* d_in, const int* in_sizes, int n_in,
                              void* d_out, int out_size) {
    const float* x   = (const float*)d_in[0];
    const float* cw  = (const float*)d_in[1];
    const float* cb  = (const float*)d_in[2];
    const float* bg  = (const float*)d_in[3];
    const float* bbn = (const float*)d_in[4];
    const float* pe  = (const float*)d_in[5];
    const float* qW  = (const float*)d_in[6];
    const float* qb  = (const float*)d_in[7];
    const float* kW  = (const float*)d_in[8];
    const float* kb  = (const float*)d_in[9];
    const float* vW  = (const float*)d_in[10];
    const float* vb  = (const float*)d_in[11];
    const float* oW  = (const float*)d_in[12];
    const float* ob  = (const float*)d_in[13];
    const float* scale = (const float*)d_in[14];
    const float* td  = (const float*)d_in[15];
    const float* ln1g = (const float*)d_in[16];
    const float* ln1b = (const float*)d_in[17];
    const float* f1W = (const float*)d_in[18];
    const float* f1b = (const float*)d_in[19];
    const float* f2W = (const float*)d_in[20];
    const float* f2b = (const float*)d_in[21];
    const float* ln2g = (const float*)d_in[22];
    const float* ln2b = (const float*)d_in[23];
    const float* outW = (const float*)d_in[24];
    const float* outb = (const float*)d_in[25];
    float* out = (float*)d_out;

    float* buf = nullptr;
    cudaGetSymbolAddress((void**)&buf, g_buf);
    float* H0 = buf;
    float* H2 = buf + 1L * NH;
    float* Qb = buf + 2L * NH;
    float* Kb = buf + 3L * NH;
    float* Vb = buf + 4L * NH;
    float* T  = buf + 5L * NH;
    float* TP = buf + 6L * NH;
    __nv_bfloat16* B16 = (__nv_bfloat16*)(buf + 7L * NH);
    __nv_bfloat16* H0h = B16;
    __nv_bfloat16* H0l = B16 + 1L * NH;
    __nv_bfloat16* H2h = B16 + 2L * NH;
    __nv_bfloat16* H2l = B16 + 3L * NH;
    __nv_bfloat16* CXh = B16 + 4L * NH;
    __nv_bfloat16* CXl = B16 + 5L * NH;
    __nv_bfloat16* FFh = B16 + 6L * NH;
    __nv_bfloat16* FFl = B16 + 6L * NH + NFF;
    __nv_bfloat16* Wb  = B16 + 6L * NH + 2L * NFF;
    float* TAIL = buf + 7L * NH + BF16_FLOATS;
    float* SMALL = TAIL + 512;
    float* Q2 = SMALL, *CTX2 = SMALL + 512, *T2 = SMALL + 1024, *R1 = SMALL + 1536;
    float* FFROW = SMALL + 2048, *T3 = SMALL + 4096, *R2 = SMALL + 4608;
    float* CS = SMALL + 5632;   // [BB][32][DD] = 16384 floats

    auto WQH = [&](int l){ return Wb + 0       + l * 65536; };
    auto WQL = [&](int l){ return Wb + 131072  + l * 65536; };
    auto WKH = [&](int l){ return Wb + 262144  + l * 65536; };
    auto WKL = [&](int l){ return Wb + 393216  + l * 65536; };
    auto WVH = [&](int l){ return Wb + 524288  + l * 65536; };
    auto WVL = [&](int l){ return Wb + 655360  + l * 65536; };
    auto WOH = [&](int l){ return Wb + 786432  + l * 65536; };
    auto WOL = [&](int l){ return Wb + 917504  + l * 65536; };
    auto WF1H = [&](int l){ return Wb + 1048576 + l * 262144; };
    auto WF1L = [&](int l){ return Wb + 1572864 + l * 262144; };
    auto WF2H = [&](int l){ return Wb + 2097152 + l * 262144; };
    auto WF2L = [&](int l){ return Wb + 2621440 + l * 262144; };

    const int M = BB * SEQL;                 // 4096
    dim3 gAttn(SEQL / 128, BB * HH);
    dim3 gCsum(BB, 32);

    // --- stem + weight split ---
    conv_pe_kernel<<<(NH + 255) / 256, 256>>>(x, cw, cb, bg, bbn, pe, H0, H0h, H0l);
    wsplit_kernel<<<dim3(128, 1, 6), 256>>>(qW, kW, vW, oW, f1W, f2W, Wb);

    // --- layer 0 ---
    {   // Q full; K,V only head rows (early-exit via tdl)
        TcJobs3 J{};
        J.j[0] = {H0h, H0l, WQH(0), WQL(0), qb, Qb, nullptr, nullptr, nullptr, DD, DD, DD, DD, 2 | 8};
        J.j[1] = {H0h, H0l, WKH(0), WKL(0), kb, Kb, nullptr, nullptr, td,      DD, DD, DD, DD, 2 | 8};
        J.j[2] = {H0h, H0l, WVH(0), WVL(0), vb, Vb, nullptr, nullptr, td,      DD, DD, DD, DD, 2 | 8};
        tc_kernel<<<dim3(DD / 64, M / 128, 3), 256>>>(J);
    }
    csum_kernel<<<gCsum, 256>>>(H0, CS);
    tailmv2_kernel<<<BB * HH, 256>>>(H0, CS, vW, vb, td, 0, TAIL);
    attn_kernel<<<gAttn, 128>>>(Qb, Kb, Vb, td, scale, TAIL, CXh, CXl, 0);
    {
        TcJobs3 J{};
        J.j[0] = {CXh, CXl, WOH(0), WOL(0), ob, T, nullptr, nullptr, nullptr, DD, DD, DD, DD, 2 | 8};
        tc_kernel<<<dim3(DD / 64, M / 128, 1), 256>>>(J);
    }
    ln_kernel<false, true><<<M, 256>>>(T, DD, nullptr, H0, DD, ln1g, ln1b, H2, DD, H2h, H2l);
    {
        TcJobs3 J{};
        J.j[0] = {H2h, H2l, WF1H(0), WF1L(0), f1b, nullptr, FFh, FFl, nullptr, DD, DD, DFFN, DD, 1 | 4 | 8};
        tc_kernel<<<dim3(DFFN / 64, M / 128, 1), 256>>>(J);
    }
    {   // FFN2 split-K=2; partials T (+bias) and TP
        TcJobs3 J{};
        J.j[0] = {FFh,       FFl,       WF2H(0),       WF2L(0),       f2b, T,  nullptr, nullptr, nullptr, DFFN, DFFN, DD, 512, 2 | 8};
        J.j[1] = {FFh + 512, FFl + 512, WF2H(0) + 512, WF2L(0) + 512, f2b, TP, nullptr, nullptr, nullptr, DFFN, DFFN, DD, 512, 2};
        tc_kernel<<<dim3(DD / 64, M / 128, 2), 256>>>(J);
    }
    ln_kernel<true, true><<<M, 256>>>(T, DD, TP, H2, DD, ln2g, ln2b, H0, DD, H0h, H0l);

    // --- layer 1 (only last token needed downstream of attention) ---
    const float* qW1 = qW + DD * DD;   const float* qb1 = qb + DD;
    const float* oW1 = oW + DD * DD;   const float* ob1 = ob + DD;
    const float* kb1 = kb + DD;        const float* vb1 = vb + DD;
    const float* ln1g1 = ln1g + DD;    const float* ln1b1 = ln1b + DD;
    const float* ln2g1 = ln2g + DD;    const float* ln2b1 = ln2b + DD;
    const float* f1W1 = f1W + DFFN * DD; const float* f1b1 = f1b + DFFN;
    const float* f2W1 = f2W + DD * DFFN; const float* f2b1 = f2b + DD;
    const float* hlast = H0 + (long)(SEQL - 1) * DD;

    {   // K,V head rows only (early-exit)
        TcJobs3 J{};
        J.j[0] = {H0h, H0l, WKH(1), WKL(1), kb1, Kb, nullptr, nullptr, td + HH, DD, DD, DD, DD, 2 | 8};
        J.j[1] = {H0h, H0l, WVH(1), WVL(1), vb1, Vb, nullptr, nullptr, td + HH, DD, DD, DD, DD, 2 | 8};
        tc_kernel<<<dim3(DD / 64, M / 128, 2), 256>>>(J);
    }
    csum_kernel<<<gCsum, 256>>>(H0, CS);
    tailmv2_kernel<<<BB * HH, 256>>>(H0, CS, vW, vb, td, 1, TAIL);

    rowgemm_kernel<false><<<dim3(BB, 1), 256, DD * 4>>>(hlast, (long)SEQL * DD, qW1, qb1, Q2, DD, DD);
    attn1_kernel<<<BB * HH, 128>>>(Q2, Kb, Vb, td, scale, TAIL, CTX2, 1);
    rowgemm_kernel<false><<<dim3(BB, 1), 256, DD * 4>>>(CTX2, DD, oW1, ob1, T2, DD, DD);
    ln_kernel<false, false><<<BB, 256>>>(T2, DD, nullptr, hlast, (long)SEQL * DD, ln1g1, ln1b1, R1, DD, nullptr, nullptr);
    rowgemm_kernel<true ><<<dim3(BB, DFFN / 256), 256, DD * 4>>>(R1, DD, f1W1, f1b1, FFROW, DD, DFFN);
    rowgemm_kernel<false><<<dim3(BB, 1), 256, DFFN * 4>>>(FFROW, DFFN, f2W1, f2b1, T3, DFFN, DD);
    ln_kernel<false, false><<<BB, 256>>>(T3, DD, nullptr, R1, DD, ln2g1, ln2b1, R2, DD, nullptr, nullptr);

    out_kernel<<<BB, 256>>>(R2, outW, outb, out);
}

// round 9
// speedup vs baseline: 1.7425x; 1.0297x over previous
#include <cuda_runtime.h>
#include <cuda_bf16.h>

#define BB 2
#define SEQL 2048
#define DD 256
#define HH 8
#define DKK 32
#define DFFN 1024
#define EPSF 1e-5f

#define NH  (BB*SEQL*DD)      /* 1048576 */
#define NFF (BB*SEQL*DFFN)    /* 4194304 */

#define BF16_FLOATS 8912896L
__device__ float g_buf[7L*NH + BF16_FLOATS + 512 + 32768];

__device__ __forceinline__ int compute_kcut(float tdh) {
    if (!(tdh > 1e-6f)) return SEQL;
    float c = 33.0f / tdh;     // exp(s * e^-33) == 1.0f exactly for |s| < 1e7
    if (c >= (float)SEQL) return SEQL;
    int k = (int)ceilf(c);
    return k < SEQL ? k : SEQL;
}

// ---------------------------------------------------------------- cp.async helpers
#define CP16(dst, src) \
    asm volatile("cp.async.cg.shared.global [%0], [%1], 16;" :: "r"(dst), "l"(src))
#define CPCOMMIT() asm volatile("cp.async.commit_group;" ::: "memory")
#define CPWAIT0() asm volatile("cp.async.wait_group 0;" ::: "memory")
#define CPWAIT1() asm volatile("cp.async.wait_group 1;" ::: "memory")

// ---------------------------------------------------------------- conv + bn + relu + pe (+ bf16 split)
__global__ void conv_pe_kernel(const float* __restrict__ x, const float* __restrict__ cw,
                               const float* __restrict__ cb, const float* __restrict__ bg,
                               const float* __restrict__ bb, const float* __restrict__ pe,
                               float* __restrict__ out,
                               __nv_bfloat16* __restrict__ oh, __nv_bfloat16* __restrict__ ol) {
    int idx = blockIdx.x * 256 + threadIdx.x;
    if (idx >= NH) return;
    int d = idx & (DD - 1);
    int t = (idx >> 8) & (SEQL - 1);
    int b = idx >> 19;
    const float* xb = x + b * SEQL;
    float xm = t > 0 ? xb[t - 1] : 0.f;
    float x0 = xb[t];
    float xp = (t < SEQL - 1) ? xb[t + 1] : 0.f;
    float v = cw[d * 3 + 0] * xm + cw[d * 3 + 1] * x0 + cw[d * 3 + 2] * xp + cb[d];
    v = v * rsqrtf(1.f + EPSF) * bg[d] + bb[d];
    v = fmaxf(v, 0.f);
    float r = v + pe[t * DD + d];
    out[idx] = r;
    __nv_bfloat16 h = __float2bfloat16(r);
    oh[idx] = h;
    ol[idx] = __float2bfloat16(r - __bfloat162float(h));
}

// ---------------------------------------------------------------- weight split fp32 -> bf16 hi/lo
__global__ void wsplit_kernel(const float* __restrict__ q, const float* __restrict__ k,
                              const float* __restrict__ v, const float* __restrict__ o,
                              const float* __restrict__ f1, const float* __restrict__ f2,
                              __nv_bfloat16* __restrict__ W) {
    int z = blockIdx.z;
    const float* src; long n; long off;
    switch (z) {
        case 0: src = q;  n = 131072; off = 0;       break;
        case 1: src = k;  n = 131072; off = 262144;  break;
        case 2: src = v;  n = 131072; off = 524288;  break;
        case 3: src = o;  n = 131072; off = 786432;  break;
        case 4: src = f1; n = 524288; off = 1048576; break;
        default: src = f2; n = 524288; off = 2097152; break;
    }
    __nv_bfloat16* dh = W + off;
    __nv_bfloat16* dl = dh + n;
    for (long i = blockIdx.x * 256L + threadIdx.x; i < n; i += (long)gridDim.x * 256L) {
        float xx = src[i];
        __nv_bfloat16 h = __float2bfloat16(xx);
        dh[i] = h;
        dl[i] = __float2bfloat16(xx - __bfloat162float(h));
    }
}

// ---------------------------------------------------------------- HMMA GEMM: C[M,N] = A[M,K] @ W[N,K]^T
struct TcJob {
    const __nv_bfloat16 *Ah, *Al;
    const __nv_bfloat16 *Wh, *Wl;
    const float* bias;
    float* C;
    __nv_bfloat16 *Ch, *Cl;
    const float* tdl;            // if set: CTA exits when (m0 & (SEQL-1)) >= max kcut
    int lda, ldw, N, K, flags;   // flags: 1=RELU 2=FP32OUT 4=BF16OUT 8=BIAS
};
struct TcJobs3 { TcJob j[3]; };

#define MMA_BF16(c, a, b) \
    asm volatile("mma.sync.aligned.m16n8k16.row.col.f32.bf16.bf16.f32 " \
        "{%0,%1,%2,%3}, {%4,%5,%6,%7}, {%8,%9}, {%0,%1,%2,%3};" \
        : "+f"((c)[0]), "+f"((c)[1]), "+f"((c)[2]), "+f"((c)[3]) \
        : "r"((a)[0]), "r"((a)[1]), "r"((a)[2]), "r"((a)[3]), "r"((b)[0]), "r"((b)[1]))

#define LDU(p) (*(const unsigned*)(p))

__global__ __launch_bounds__(256) void tc_kernel(TcJobs3 jobs) {
    TcJob jb = jobs.j[blockIdx.z];
    const int m0 = blockIdx.y * 128, n0 = blockIdx.x * 64;
    if (jb.tdl) {
        int kmax = 0;
#pragma unroll
        for (int h = 0; h < HH; h++) {
            int kc = compute_kcut(jb.tdl[h]);
            kmax = kc > kmax ? kc : kmax;
        }
        if ((m0 & (SEQL - 1)) >= kmax) return;   // rows unused downstream
    }
    __shared__ __nv_bfloat16 sA[2][2][128][40];   // [stage][hi/lo][row][k+pad]
    __shared__ __nv_bfloat16 sB[2][2][64][40];
    const int tid = threadIdx.x, wid = tid >> 5, lane = tid & 31;
    const int wm = (wid & 3) * 32, wn = (wid >> 2) * 32;
    const int g = lane >> 2, tg = lane & 3;

    float acc[2][4][4];
#pragma unroll
    for (int mi = 0; mi < 2; mi++)
#pragma unroll
        for (int ni = 0; ni < 4; ni++)
#pragma unroll
            for (int r = 0; r < 4; r++) acc[mi][ni][r] = 0.f;

    const int arow = tid >> 1, ac = tid & 1;          // A: 2 rows' worth per iter pair
    const int brow = tid >> 2, bc8 = tid & 3;
    const int nkb = jb.K >> 5;

    // issue cp.async loads for k-block `it` into stage it&1
    auto issue = [&](int it) {
        const int buf = it & 1;
        const int kb = it << 5;
#pragma unroll
        for (int i = 0; i < 2; i++) {
            int idx = i * 256 + tid;
            int rr = idx >> 2, cc = idx & 3;
            size_t go = (size_t)(m0 + rr) * jb.lda + kb + cc * 8;
            CP16((unsigned)__cvta_generic_to_shared(&sA[buf][0][rr][cc * 8]), jb.Ah + go);
            CP16((unsigned)__cvta_generic_to_shared(&sA[buf][1][rr][cc * 8]), jb.Al + go);
        }
        {
            size_t go = (size_t)(n0 + brow) * jb.ldw + kb + bc8 * 8;
            CP16((unsigned)__cvta_generic_to_shared(&sB[buf][0][brow][bc8 * 8]), jb.Wh + go);
            CP16((unsigned)__cvta_generic_to_shared(&sB[buf][1][brow][bc8 * 8]), jb.Wl + go);
        }
        CPCOMMIT();
    };

    issue(0);
    for (int it = 0; it < nkb; ++it) {
        const int buf = it & 1;
        if (it + 1 < nkb) {
            issue(it + 1);
            CPWAIT1();
        } else {
            CPWAIT0();
        }
        __syncthreads();

#pragma unroll
        for (int ks = 0; ks < 2; ks++) {
            const int k0 = ks * 16;
            unsigned ah[2][4], al[2][4];
#pragma unroll
            for (int mi = 0; mi < 2; mi++) {
                int r = wm + mi * 16 + g;
                ah[mi][0] = LDU(&sA[buf][0][r][k0 + 2 * tg]);
                ah[mi][1] = LDU(&sA[buf][0][r + 8][k0 + 2 * tg]);
                ah[mi][2] = LDU(&sA[buf][0][r][k0 + 2 * tg + 8]);
                ah[mi][3] = LDU(&sA[buf][0][r + 8][k0 + 2 * tg + 8]);
                al[mi][0] = LDU(&sA[buf][1][r][k0 + 2 * tg]);
                al[mi][1] = LDU(&sA[buf][1][r + 8][k0 + 2 * tg]);
                al[mi][2] = LDU(&sA[buf][1][r][k0 + 2 * tg + 8]);
                al[mi][3] = LDU(&sA[buf][1][r + 8][k0 + 2 * tg + 8]);
            }
            unsigned bh[4][2], bl[4][2];
#pragma unroll
            for (int ni = 0; ni < 4; ni++) {
                int rn = wn + ni * 8 + g;
                bh[ni][0] = LDU(&sB[buf][0][rn][k0 + 2 * tg]);
                bh[ni][1] = LDU(&sB[buf][0][rn][k0 + 2 * tg + 8]);
                bl[ni][0] = LDU(&sB[buf][1][rn][k0 + 2 * tg]);
                bl[ni][1] = LDU(&sB[buf][1][rn][k0 + 2 * tg + 8]);
            }
#pragma unroll
            for (int mi = 0; mi < 2; mi++)
#pragma unroll
                for (int ni = 0; ni < 4; ni++) {
                    MMA_BF16(acc[mi][ni], ah[mi], bh[ni]);
                    MMA_BF16(acc[mi][ni], ah[mi], bl[ni]);
                    MMA_BF16(acc[mi][ni], al[mi], bh[ni]);
                }
        }
        __syncthreads();
    }

    const bool hasb = (jb.flags & 8), rl = (jb.flags & 1);
#pragma unroll
    for (int mi = 0; mi < 2; mi++) {
#pragma unroll
        for (int ni = 0; ni < 4; ni++) {
            int r0 = m0 + wm + mi * 16 + g;
            int r1 = r0 + 8;
            int cb = n0 + wn + ni * 8 + 2 * tg;
            float v0 = acc[mi][ni][0], v1 = acc[mi][ni][1];
            float v2 = acc[mi][ni][2], v3 = acc[mi][ni][3];
            if (hasb) {
                float b0 = jb.bias[cb], b1 = jb.bias[cb + 1];
                v0 += b0; v1 += b1; v2 += b0; v3 += b1;
            }
            if (rl) {
                v0 = fmaxf(v0, 0.f); v1 = fmaxf(v1, 0.f);
                v2 = fmaxf(v2, 0.f); v3 = fmaxf(v3, 0.f);
            }
            if (jb.flags & 2) {
                *(float2*)(jb.C + (size_t)r0 * jb.N + cb) = make_float2(v0, v1);
                *(float2*)(jb.C + (size_t)r1 * jb.N + cb) = make_float2(v2, v3);
            }
            if (jb.flags & 4) {
                __nv_bfloat162 h0, l0, h1, l1;
                h0.x = __float2bfloat16(v0); h0.y = __float2bfloat16(v1);
                l0.x = __float2bfloat16(v0 - __bfloat162float(h0.x));
                l0.y = __float2bfloat16(v1 - __bfloat162float(h0.y));
                h1.x = __float2bfloat16(v2); h1.y = __float2bfloat16(v3);
                l1.x = __float2bfloat16(v2 - __bfloat162float(h1.x));
                l1.y = __float2bfloat16(v3 - __bfloat162float(h1.y));
                *(__nv_bfloat162*)(jb.Ch + (size_t)r0 * jb.N + cb) = h0;
                *(__nv_bfloat162*)(jb.Cl + (size_t)r0 * jb.N + cb) = l0;
                *(__nv_bfloat162*)(jb.Ch + (size_t)r1 * jb.N + cb) = h1;
                *(__nv_bfloat162*)(jb.Cl + (size_t)r1 * jb.N + cb) = l1;
            }
        }
    }
}

// ---------------------------------------------------------------- chunk sums of H (float4, 4 row-groups x 64 lanes)
__global__ __launch_bounds__(256)
void csum_kernel(const float* __restrict__ H, float* __restrict__ CS) {
    __shared__ float4 sm[4][64];
    int b = blockIdx.x, c = blockIdx.y;
    int t = threadIdx.x;
    int d4 = t & 63;       // float4 column
    int rg = t >> 6;       // row group 0..3 (16 rows each)
    const float4* p = (const float4*)(H + ((long)b * SEQL + c * 64 + rg * 16) * DD) + d4;
    float4 s = make_float4(0.f, 0.f, 0.f, 0.f);
#pragma unroll
    for (int r = 0; r < 16; ++r) {
        float4 v = p[(long)r * 64];
        s.x += v.x; s.y += v.y; s.z += v.z; s.w += v.w;
    }
    sm[rg][d4] = s;
    __syncthreads();
    if (rg == 0) {
        float4 a = sm[0][d4], b1 = sm[1][d4], c1 = sm[2][d4], d1 = sm[3][d4];
        float4 o;
        o.x = (a.x + b1.x) + (c1.x + d1.x);
        o.y = (a.y + b1.y) + (c1.y + d1.y);
        o.z = (a.z + b1.z) + (c1.z + d1.z);
        o.w = (a.w + b1.w) + (c1.w + d1.w);
        ((float4*)(CS + ((long)b * 32 + c) * DD))[d4] = o;
    }
}

// ---------------------------------------------------------------- tailV[b,h,d] from chunk sums + boundary rows, fused matvec vs vW
__global__ __launch_bounds__(256)
void tailmv2_kernel(const float* __restrict__ H, const float* __restrict__ CS,
                    const float* __restrict__ vW, const float* __restrict__ vb,
                    const float* __restrict__ td, int l, float* __restrict__ tailV) {
    __shared__ float sfx[DD];
    __shared__ float red[DKK][8];
    int bh = blockIdx.x;
    int b = bh / HH, h = bh % HH;
    int tid = threadIdx.x;
    int kcut = compute_kcut(td[l * HH + h]);
    int cb = kcut >> 6;
    int cend = (cb + 1) << 6; if (cend > SEQL) cend = SEQL;
    float s = 0.f;
    for (int k = kcut; k < cend; ++k) s += H[((long)b * SEQL + k) * DD + tid];
    for (int c = cb + 1; c < 32; ++c) s += CS[((long)b * 32 + c) * DD + tid];
    sfx[tid] = s;
    __syncthreads();
    int dl = tid & 31, grp = tid >> 5;
    int n = h * DKK + dl;
    const float* w = vW + (long)l * DD * DD + (long)n * DD + grp * 32;
    const float* sv = sfx + grp * 32;
    float p = 0.f;
#pragma unroll
    for (int j = 0; j < 32; ++j) p = fmaf(sv[j], w[j], p);
    red[dl][grp] = p;
    __syncthreads();
    if (tid < DKK) {
        float t = 0.f;
#pragma unroll
        for (int gi = 0; gi < 8; gi++) t += red[tid][gi];
        tailV[bh * DKK + tid] = t + (float)(SEQL - kcut) * vb[l * DD + h * DKK + tid];
    }
}

// ---------------------------------------------------------------- attention (emits bf16 hi/lo ctx)
__global__ __launch_bounds__(128)
void attn_kernel(const float* __restrict__ Q, const float* __restrict__ Km,
                 const float* __restrict__ Vm, const float* __restrict__ td,
                 const float* __restrict__ scale, const float* __restrict__ tailV,
                 __nv_bfloat16* __restrict__ Ch, __nv_bfloat16* __restrict__ Cl, int l) {
    __shared__ float Ks[128][DKK];
    __shared__ float Vs[128][DKK];
    __shared__ float dec[128];
    int bh = blockIdx.y;
    int b = bh / HH, h = bh % HH;
    int tid = threadIdx.x;
    int q = blockIdx.x * 128 + tid;
    float tdh = td[l * HH + h];
    int kcut = compute_kcut(tdh);
    float c = scale[l] * rsqrtf((float)DKK);
    float4 qv[8];
    {
        const float4* qp = (const float4*)(Q + ((long)(b * SEQL + q)) * DD + h * DKK);
#pragma unroll
        for (int j = 0; j < 8; ++j) {
            float4 t = qp[j];
            t.x *= c; t.y *= c; t.z *= c; t.w *= c;
            qv[j] = t;
        }
    }
    float Z = 0.f;
    float4 cx[8];
#pragma unroll
    for (int j = 0; j < 8; ++j) cx[j] = make_float4(0.f, 0.f, 0.f, 0.f);

    for (int kb = 0; kb < kcut; kb += 128) {
        int kn = min(128, kcut - kb);
        __syncthreads();
        const float4* Kg = (const float4*)(Km + ((long)(b * SEQL + kb)) * DD + h * DKK);
        const float4* Vg = (const float4*)(Vm + ((long)(b * SEQL + kb)) * DD + h * DKK);
#pragma unroll
        for (int i = 0; i < 8; i++) {
            int idx = i * 128 + tid;
            int r = idx >> 3, c4 = idx & 7;
            if (r < kn) {
                ((float4*)Ks[r])[c4] = Kg[(long)r * (DD / 4) + c4];
                ((float4*)Vs[r])[c4] = Vg[(long)r * (DD / 4) + c4];
            }
        }
        if (tid < kn) dec[tid] = __expf(-tdh * (float)(kb + tid));
        __syncthreads();
        for (int kk = 0; kk < kn; ++kk) {
            const float4* kr = (const float4*)Ks[kk];
            float s0 = 0.f, s1 = 0.f, s2 = 0.f, s3 = 0.f;
#pragma unroll
            for (int j = 0; j < 8; j += 2) {
                float4 k0 = kr[j], k1 = kr[j + 1];
                s0 = fmaf(qv[j].x, k0.x, s0); s1 = fmaf(qv[j].y, k0.y, s1);
                s2 = fmaf(qv[j].z, k0.z, s2); s3 = fmaf(qv[j].w, k0.w, s3);
                s0 = fmaf(qv[j + 1].x, k1.x, s0); s1 = fmaf(qv[j + 1].y, k1.y, s1);
                s2 = fmaf(qv[j + 1].z, k1.z, s2); s3 = fmaf(qv[j + 1].w, k1.w, s3);
            }
            float s = ((s0 + s1) + (s2 + s3)) * dec[kk];
            float e = __expf(s);
            float w = e * e / (1.f + e);
            Z += e;
            const float4* vr = (const float4*)Vs[kk];
#pragma unroll
            for (int j = 0; j < 8; ++j) {
                float4 vv = vr[j];
                cx[j].x = fmaf(w, vv.x, cx[j].x);
                cx[j].y = fmaf(w, vv.y, cx[j].y);
                cx[j].z = fmaf(w, vv.z, cx[j].z);
                cx[j].w = fmaf(w, vv.w, cx[j].w);
            }
        }
    }
    Z += (float)(SEQL - kcut);
    float invZ = 1.f / Z;
    const float4* tv = (const float4*)(tailV + bh * DKK);
    size_t ob = ((size_t)(b * SEQL + q)) * DD + h * DKK;
#pragma unroll
    for (int j = 0; j < 8; ++j) {
        float4 t = tv[j];
        float ov[4];
        ov[0] = (cx[j].x + 0.5f * t.x) * invZ;
        ov[1] = (cx[j].y + 0.5f * t.y) * invZ;
        ov[2] = (cx[j].z + 0.5f * t.z) * invZ;
        ov[3] = (cx[j].w + 0.5f * t.w) * invZ;
#pragma unroll
        for (int u = 0; u < 4; ++u) {
            __nv_bfloat16 hh = __float2bfloat16(ov[u]);
            Ch[ob + j * 4 + u] = hh;
            Cl[ob + j * 4 + u] = __float2bfloat16(ov[u] - __bfloat162float(hh));
        }
    }
}

// ---------------------------------------------------------------- single-query attention (layer 2 last token)
__global__ __launch_bounds__(128)
void attn1_kernel(const float* __restrict__ q2, const float* __restrict__ Km,
                  const float* __restrict__ Vm, const float* __restrict__ td,
                  const float* __restrict__ scale, const float* __restrict__ tailV,
                  float* __restrict__ ctx2, int l) {
    int b = blockIdx.x / HH, h = blockIdx.x % HH;
    int tid = threadIdx.x;
    float tdh = td[l * HH + h];
    int kcut = compute_kcut(tdh);
    float c = scale[l] * rsqrtf((float)DKK);
    __shared__ float qs[DKK];
    __shared__ float ws[128];
    __shared__ float red[4];
    if (tid < DKK) qs[tid] = q2[b * DD + h * DKK + tid] * c;
    __syncthreads();
    float Zp = 0.f;
    float cxd = 0.f;
    for (int kb = 0; kb < kcut; kb += 128) {
        int kn = min(128, kcut - kb);
        float w = 0.f;
        if (tid < kn) {
            int k = kb + tid;
            const float* kr = Km + ((long)(b * SEQL + k)) * DD + h * DKK;
            float s = 0.f;
#pragma unroll
            for (int d = 0; d < DKK; ++d) s = fmaf(qs[d], kr[d], s);
            s *= __expf(-tdh * (float)k);
            float e = __expf(s);
            w = e * e / (1.f + e);
            Zp += e;
        }
        __syncthreads();
        ws[tid] = w;
        __syncthreads();
        if (tid < DKK) {
            for (int kk = 0; kk < kn; ++kk)
                cxd = fmaf(ws[kk], Vm[((long)(b * SEQL + kb + kk)) * DD + h * DKK + tid], cxd);
        }
        __syncthreads();
    }
    float s = Zp;
#pragma unroll
    for (int o = 16; o; o >>= 1) s += __shfl_xor_sync(0xffffffffu, s, o);
    if ((tid & 31) == 0) red[tid >> 5] = s;
    __syncthreads();
    float Z = red[0] + red[1] + red[2] + red[3] + (float)(SEQL - kcut);
    if (tid < DKK)
        ctx2[b * DD + h * DKK + tid] = (cxd + 0.5f * tailV[blockIdx.x * DKK + tid]) / Z;
}

// ---------------------------------------------------------------- small-M GEMM (M=2 rows), fp32
template <bool RELU>
__global__ void rowgemm_kernel(const float* __restrict__ A, long lda,
                               const float* __restrict__ W, const float* __restrict__ bias,
                               float* __restrict__ C, int K, int N) {
    extern __shared__ float arow[];
    int m = blockIdx.x;
    int n = blockIdx.y * blockDim.x + threadIdx.x;
    for (int i = threadIdx.x; i < K; i += blockDim.x) arow[i] = A[(long)m * lda + i];
    __syncthreads();
    float s = bias[n];
    const float* wr = W + (long)n * K;
#pragma unroll 4
    for (int kk = 0; kk < K; ++kk) s = fmaf(arow[kk], wr[kk], s);
    if (RELU) s = fmaxf(s, 0.f);
    C[(long)m * N + n] = s;
}

// ---------------------------------------------------------------- residual + layernorm; optional 2nd partial + bf16 emit
template <bool TWO, bool EMIT>
__global__ void ln_kernel(const float* __restrict__ z, long zs,
                          const float* __restrict__ z2,
                          const float* __restrict__ res, long rs,
                          const float* __restrict__ g, const float* __restrict__ be,
                          float* __restrict__ out, long os,
                          __nv_bfloat16* __restrict__ oh, __nv_bfloat16* __restrict__ ol) {
    int m = blockIdx.x, t = threadIdx.x;
    float v = z[(long)m * zs + t] + res[(long)m * rs + t];
    if (TWO) v += z2[(long)m * zs + t];
    __shared__ float sm[8];
    float s = v;
#pragma unroll
    for (int o = 16; o; o >>= 1) s += __shfl_xor_sync(0xffffffffu, s, o);
    if ((t & 31) == 0) sm[t >> 5] = s;
    __syncthreads();
    float tot = 0.f;
#pragma unroll
    for (int i = 0; i < 8; i++) tot += sm[i];
    float mean = tot * (1.0f / DD);
    float dv = v - mean;
    float s2 = dv * dv;
    __syncthreads();
#pragma unroll
    for (int o = 16; o; o >>= 1) s2 += __shfl_xor_sync(0xffffffffu, s2, o);
    if ((t & 31) == 0) sm[t >> 5] = s2;
    __syncthreads();
    float var = 0.f;
#pragma unroll
    for (int i = 0; i < 8; i++) var += sm[i];
    var *= (1.0f / DD);
    float o = dv * rsqrtf(var + EPSF) * g[t] + be[t];
    out[(long)m * os + t] = o;
    if (EMIT) {
        __nv_bfloat16 hh = __float2bfloat16(o);
        oh[(long)m * DD + t] = hh;
        ol[(long)m * DD + t] = __float2bfloat16(o - __bfloat162float(hh));
    }
}

// ---------------------------------------------------------------- final projection
__global__ void out_kernel(const float* __restrict__ r2, const float* __restrict__ ow,
                           const float* __restrict__ ob, float* __restrict__ out) {
    int b = blockIdx.x, t = threadIdx.x;
    float p = r2[b * DD + t] * ow[t];
    __shared__ float sm[8];
    float s = p;
#pragma unroll
    for (int o = 16; o; o >>= 1) s += __shfl_xor_sync(0xffffffffu, s, o);
    if ((t & 31) == 0) sm[t >> 5] = s;
    __syncthreads();
    if (t == 0) {
        float tot = 0.f;
#pragma unroll
        for (int i = 0; i < 8; i++) tot += sm[i];
        out[b] = 0.5f * tot + ob[0];
    }
}

// ================================================================ host orchestration
extern "C" void kernel_launch(void* const* d_in, const int* in_sizes, int n_in,
                              void* d_out, int out_size) {
    const float* x   = (const float*)d_in[0];
    const float* cw  = (const float*)d_in[1];
    const float* cb  = (const float*)d_in[2];
    const float* bg  = (const float*)d_in[3];
    const float* bbn = (const float*)d_in[4];
    const float* pe  = (const float*)d_in[5];
    const float* qW  = (const float*)d_in[6];
    const float* qb  = (const float*)d_in[7];
    const float* kW  = (const float*)d_in[8];
    const float* kb  = (const float*)d_in[9];
    const float* vW  = (const float*)d_in[10];
    const float* vb  = (const float*)d_in[11];
    const float* oW  = (const float*)d_in[12];
    const float* ob  = (const float*)d_in[13];
    const float* scale = (const float*)d_in[14];
    const float* td  = (const float*)d_in[15];
    const float* ln1g = (const float*)d_in[16];
    const float* ln1b = (const float*)d_in[17];
    const float* f1W = (const float*)d_in[18];
    const float* f1b = (const float*)d_in[19];
    const float* f2W = (const float*)d_in[20];
    const float* f2b = (const float*)d_in[21];
    const float* ln2g = (const float*)d_in[22];
    const float* ln2b = (const float*)d_in[23];
    const float* outW = (const float*)d_in[24];
    const float* outb = (const float*)d_in[25];
    float* out = (float*)d_out;

    float* buf = nullptr;
    cudaGetSymbolAddress((void**)&buf, g_buf);
    float* H0 = buf;
    float* H2 = buf + 1L * NH;
    float* Qb = buf + 2L * NH;
    float* Kb = buf + 3L * NH;
    float* Vb = buf + 4L * NH;
    float* T  = buf + 5L * NH;
    float* TP = buf + 6L * NH;
    __nv_bfloat16* B16 = (__nv_bfloat16*)(buf + 7L * NH);
    __nv_bfloat16* H0h = B16;
    __nv_bfloat16* H0l = B16 + 1L * NH;
    __nv_bfloat16* H2h = B16 + 2L * NH;
    __nv_bfloat16* H2l = B16 + 3L * NH;
    __nv_bfloat16* CXh = B16 + 4L * NH;
    __nv_bfloat16* CXl = B16 + 5L * NH;
    __nv_bfloat16* FFh = B16 + 6L * NH;
    __nv_bfloat16* FFl = B16 + 6L * NH + NFF;
    __nv_bfloat16* Wb  = B16 + 6L * NH + 2L * NFF;
    float* TAIL = buf + 7L * NH + BF16_FLOATS;
    float* SMALL = TAIL + 512;
    float* Q2 = SMALL, *CTX2 = SMALL + 512, *T2 = SMALL + 1024, *R1 = SMALL + 1536;
    float* FFROW = SMALL + 2048, *T3 = SMALL + 4096, *R2 = SMALL + 4608;
    float* CS = SMALL + 5632;   // [BB][32][DD] = 16384 floats

    auto WQH = [&](int l){ return Wb + 0       + l * 65536; };
    auto WQL = [&](int l){ return Wb + 131072  + l * 65536; };
    auto WKH = [&](int l){ return Wb + 262144  + l * 65536; };
    auto WKL = [&](int l){ return Wb + 393216  + l * 65536; };
    auto WVH = [&](int l){ return Wb + 524288  + l * 65536; };
    auto WVL = [&](int l){ return Wb + 655360  + l * 65536; };
    auto WOH = [&](int l){ return Wb + 786432  + l * 65536; };
    auto WOL = [&](int l){ return Wb + 917504  + l * 65536; };
    auto WF1H = [&](int l){ return Wb + 1048576 + l * 262144; };
    auto WF1L = [&](int l){ return Wb + 1572864 + l * 262144; };
    auto WF2H = [&](int l){ return Wb + 2097152 + l * 262144; };
    auto WF2L = [&](int l){ return Wb + 2621440 + l * 262144; };

    const int M = BB * SEQL;                 // 4096
    dim3 gAttn(SEQL / 128, BB * HH);
    dim3 gCsum(BB, 32);

    // --- stem + weight split ---
    conv_pe_kernel<<<(NH + 255) / 256, 256>>>(x, cw, cb, bg, bbn, pe, H0, H0h, H0l);
    wsplit_kernel<<<dim3(128, 1, 6), 256>>>(qW, kW, vW, oW, f1W, f2W, Wb);

    // --- layer 0 ---
    {   // Q full; K,V only head rows (early-exit via tdl)
        TcJobs3 J{};
        J.j[0] = {H0h, H0l, WQH(0), WQL(0), qb, Qb, nullptr, nullptr, nullptr, DD, DD, DD, DD, 2 | 8};
        J.j[1] = {H0h, H0l, WKH(0), WKL(0), kb, Kb, nullptr, nullptr, td,      DD, DD, DD, DD, 2 | 8};
        J.j[2] = {H0h, H0l, WVH(0), WVL(0), vb, Vb, nullptr, nullptr, td,      DD, DD, DD, DD, 2 | 8};
        tc_kernel<<<dim3(DD / 64, M / 128, 3), 256>>>(J);
    }
    csum_kernel<<<gCsum, 256>>>(H0, CS);
    tailmv2_kernel<<<BB * HH, 256>>>(H0, CS, vW, vb, td, 0, TAIL);
    attn_kernel<<<gAttn, 128>>>(Qb, Kb, Vb, td, scale, TAIL, CXh, CXl, 0);
    {
        TcJobs3 J{};
        J.j[0] = {CXh, CXl, WOH(0), WOL(0), ob, T, nullptr, nullptr, nullptr, DD, DD, DD, DD, 2 | 8};
        tc_kernel<<<dim3(DD / 64, M / 128, 1), 256>>>(J);
    }
    ln_kernel<false, true><<<M, 256>>>(T, DD, nullptr, H0, DD, ln1g, ln1b, H2, DD, H2h, H2l);
    {
        TcJobs3 J{};
        J.j[0] = {H2h, H2l, WF1H(0), WF1L(0), f1b, nullptr, FFh, FFl, nullptr, DD, DD, DFFN, DD, 1 | 4 | 8};
        tc_kernel<<<dim3(DFFN / 64, M / 128, 1), 256>>>(J);
    }
    {   // FFN2 split-K=2; partials T (+bias) and TP
        TcJobs3 J{};
        J.j[0] = {FFh,       FFl,       WF2H(0),       WF2L(0),       f2b, T,  nullptr, nullptr, nullptr, DFFN, DFFN, DD, 512, 2 | 8};
        J.j[1] = {FFh + 512, FFl + 512, WF2H(0) + 512, WF2L(0) + 512, f2b, TP, nullptr, nullptr, nullptr, DFFN, DFFN, DD, 512, 2};
        tc_kernel<<<dim3(DD / 64, M / 128, 2), 256>>>(J);
    }
    ln_kernel<true, true><<<M, 256>>>(T, DD, TP, H2, DD, ln2g, ln2b, H0, DD, H0h, H0l);

    // --- layer 1 (only last token needed downstream of attention) ---
    const float* qW1 = qW + DD * DD;   const float* qb1 = qb + DD;
    const float* oW1 = oW + DD * DD;   const float* ob1 = ob + DD;
    const float* kb1 = kb + DD;        const float* vb1 = vb + DD;
    const float* ln1g1 = ln1g + DD;    const float* ln1b1 = ln1b + DD;
    const float* ln2g1 = ln2g + DD;    const float* ln2b1 = ln2b + DD;
    const float* f1W1 = f1W + DFFN * DD; const float* f1b1 = f1b + DFFN;
    const float* f2W1 = f2W + DD * DFFN; const float* f2b1 = f2b + DD;
    const float* hlast = H0 + (long)(SEQL - 1) * DD;

    {   // K,V head rows only (early-exit)
        TcJobs3 J{};
        J.j[0] = {H0h, H0l, WKH(1), WKL(1), kb1, Kb, nullptr, nullptr, td + HH, DD, DD, DD, DD, 2 | 8};
        J.j[1] = {H0h, H0l, WVH(1), WVL(1), vb1, Vb, nullptr, nullptr, td + HH, DD, DD, DD, DD, 2 | 8};
        tc_kernel<<<dim3(DD / 64, M / 128, 2), 256>>>(J);
    }
    csum_kernel<<<gCsum, 256>>>(H0, CS);
    tailmv2_kernel<<<BB * HH, 256>>>(H0, CS, vW, vb, td, 1, TAIL);

    rowgemm_kernel<false><<<dim3(BB, 1), 256, DD * 4>>>(hlast, (long)SEQL * DD, qW1, qb1, Q2, DD, DD);
    attn1_kernel<<<BB * HH, 128>>>(Q2, Kb, Vb, td, scale, TAIL, CTX2, 1);
    rowgemm_kernel<false><<<dim3(BB, 1), 256, DD * 4>>>(CTX2, DD, oW1, ob1, T2, DD, DD);
    ln_kernel<false, false><<<BB, 256>>>(T2, DD, nullptr, hlast, (long)SEQL * DD, ln1g1, ln1b1, R1, DD, nullptr, nullptr);
    rowgemm_kernel<true ><<<dim3(BB, DFFN / 256), 256, DD * 4>>>(R1, DD, f1W1, f1b1, FFROW, DD, DFFN);
    rowgemm_kernel<false><<<dim3(BB, 1), 256, DFFN * 4>>>(FFROW, DFFN, f2W1, f2b1, T3, DFFN, DD);
    ln_kernel<false, false><<<BB, 256>>>(T3, DD, nullptr, R1, DD, ln2g1, ln2b1, R2, DD, nullptr, nullptr);

    out_kernel<<<BB, 256>>>(R2, outW, outb, out);
}

// round 10
// speedup vs baseline: 1.8217x; 1.0454x over previous
#include <cuda_runtime.h>
#include <cuda_fp16.h>

#define BB 2
#define SEQL 2048
#define DD 256
#define HH 8
#define DKK 32
#define DFFN 1024
#define EPSF 1e-5f

#define NH  (BB*SEQL*DD)      /* 1048576 */
#define NFF (BB*SEQL*DFFN)    /* 4194304 */

#define HALF_FLOATS 8912896L
__device__ float g_buf[7L*NH + HALF_FLOATS + 512 + 32768];

__device__ __forceinline__ int compute_kcut(float tdh) {
    if (!(tdh > 1e-6f)) return SEQL;
    float c = 33.0f / tdh;     // exp(s * e^-33) == 1.0f exactly for |s| < 1e7
    if (c >= (float)SEQL) return SEQL;
    int k = (int)ceilf(c);
    return k < SEQL ? k : SEQL;
}

// ---------------------------------------------------------------- cp.async helpers
#define CP16(dst, src) \
    asm volatile("cp.async.cg.shared.global [%0], [%1], 16;" :: "r"(dst), "l"(src))
#define CPCOMMIT() asm volatile("cp.async.commit_group;" ::: "memory")
#define CPWAIT0() asm volatile("cp.async.wait_group 0;" ::: "memory")
#define CPWAIT1() asm volatile("cp.async.wait_group 1;" ::: "memory")

__device__ __forceinline__ void split16(float x, __half& h, __half& l) {
    h = __float2half(x);
    l = __float2half(x - __half2float(h));
}

// ---------------------------------------------------------------- conv + bn + relu + pe (+ fp16 split)
__global__ void conv_pe_kernel(const float* __restrict__ x, const float* __restrict__ cw,
                               const float* __restrict__ cb, const float* __restrict__ bg,
                               const float* __restrict__ bb, const float* __restrict__ pe,
                               float* __restrict__ out,
                               __half* __restrict__ oh, __half* __restrict__ ol) {
    int idx = blockIdx.x * 256 + threadIdx.x;
    if (idx >= NH) return;
    int d = idx & (DD - 1);
    int t = (idx >> 8) & (SEQL - 1);
    int b = idx >> 19;
    const float* xb = x + b * SEQL;
    float xm = t > 0 ? xb[t - 1] : 0.f;
    float x0 = xb[t];
    float xp = (t < SEQL - 1) ? xb[t + 1] : 0.f;
    float v = cw[d * 3 + 0] * xm + cw[d * 3 + 1] * x0 + cw[d * 3 + 2] * xp + cb[d];
    v = v * rsqrtf(1.f + EPSF) * bg[d] + bb[d];
    v = fmaxf(v, 0.f);
    float r = v + pe[t * DD + d];
    out[idx] = r;
    __half h, l;
    split16(r, h, l);
    oh[idx] = h;
    ol[idx] = l;
}

// ---------------------------------------------------------------- weight convert fp32 -> fp16 (single)
__global__ void wsplit_kernel(const float* __restrict__ q, const float* __restrict__ k,
                              const float* __restrict__ v, const float* __restrict__ o,
                              const float* __restrict__ f1, const float* __restrict__ f2,
                              __half* __restrict__ W) {
    int z = blockIdx.z;
    const float* src; long n; long off;
    switch (z) {
        case 0: src = q;  n = 131072; off = 0;       break;
        case 1: src = k;  n = 131072; off = 131072;  break;
        case 2: src = v;  n = 131072; off = 262144;  break;
        case 3: src = o;  n = 131072; off = 393216;  break;
        case 4: src = f1; n = 524288; off = 524288;  break;
        default: src = f2; n = 524288; off = 1048576; break;
    }
    __half* dh = W + off;
    for (long i = blockIdx.x * 256L + threadIdx.x; i < n; i += (long)gridDim.x * 256L)
        dh[i] = __float2half(src[i]);
}

// ---------------------------------------------------------------- HMMA GEMM: C[M,N] = A[M,K] @ W[N,K]^T
// A as fp16 hi/lo split (2-pass), W single fp16; fp32 accumulate.
struct TcJob {
    const __half *Ah, *Al;
    const __half *Wh;
    const float* bias;
    float* C;
    __half *Ch, *Cl;
    const float* tdl;            // if set: CTA exits when (m0 & (SEQL-1)) >= max kcut
    int lda, ldw, N, K, flags;   // flags: 1=RELU 2=FP32OUT 4=F16OUT 8=BIAS
};
struct TcJobs3 { TcJob j[3]; };

#define MMA_F16(c, a, b) \
    asm volatile("mma.sync.aligned.m16n8k16.row.col.f32.f16.f16.f32 " \
        "{%0,%1,%2,%3}, {%4,%5,%6,%7}, {%8,%9}, {%0,%1,%2,%3};" \
        : "+f"((c)[0]), "+f"((c)[1]), "+f"((c)[2]), "+f"((c)[3]) \
        : "r"((a)[0]), "r"((a)[1]), "r"((a)[2]), "r"((a)[3]), "r"((b)[0]), "r"((b)[1]))

#define LDU(p) (*(const unsigned*)(p))

__global__ __launch_bounds__(256) void tc_kernel(TcJobs3 jobs) {
    TcJob jb = jobs.j[blockIdx.z];
    const int m0 = blockIdx.y * 128, n0 = blockIdx.x * 64;
    if (jb.tdl) {
        int kmax = 0;
#pragma unroll
        for (int h = 0; h < HH; h++) {
            int kc = compute_kcut(jb.tdl[h]);
            kmax = kc > kmax ? kc : kmax;
        }
        if ((m0 & (SEQL - 1)) >= kmax) return;   // rows unused downstream
    }
    __shared__ __half sA[2][2][128][40];   // [stage][hi/lo][row][k+pad]
    __shared__ __half sB[2][64][40];       // [stage][row][k+pad]
    const int tid = threadIdx.x, wid = tid >> 5, lane = tid & 31;
    const int wm = (wid & 3) * 32, wn = (wid >> 2) * 32;
    const int g = lane >> 2, tg = lane & 3;

    float acc[2][4][4];
#pragma unroll
    for (int mi = 0; mi < 2; mi++)
#pragma unroll
        for (int ni = 0; ni < 4; ni++)
#pragma unroll
            for (int r = 0; r < 4; r++) acc[mi][ni][r] = 0.f;

    const int brow = tid >> 2, bc8 = tid & 3;
    const int nkb = jb.K >> 5;

    auto issue = [&](int it) {
        const int buf = it & 1;
        const int kb = it << 5;
#pragma unroll
        for (int i = 0; i < 2; i++) {
            int idx = i * 256 + tid;
            int rr = idx >> 2, cc = idx & 3;
            size_t go = (size_t)(m0 + rr) * jb.lda + kb + cc * 8;
            CP16((unsigned)__cvta_generic_to_shared(&sA[buf][0][rr][cc * 8]), jb.Ah + go);
            CP16((unsigned)__cvta_generic_to_shared(&sA[buf][1][rr][cc * 8]), jb.Al + go);
        }
        {
            size_t go = (size_t)(n0 + brow) * jb.ldw + kb + bc8 * 8;
            CP16((unsigned)__cvta_generic_to_shared(&sB[buf][brow][bc8 * 8]), jb.Wh + go);
        }
        CPCOMMIT();
    };

    issue(0);
    for (int it = 0; it < nkb; ++it) {
        const int buf = it & 1;
        if (it + 1 < nkb) {
            issue(it + 1);
            CPWAIT1();
        } else {
            CPWAIT0();
        }
        __syncthreads();

#pragma unroll
        for (int ks = 0; ks < 2; ks++) {
            const int k0 = ks * 16;
            unsigned ah[2][4], al[2][4];
#pragma unroll
            for (int mi = 0; mi < 2; mi++) {
                int r = wm + mi * 16 + g;
                ah[mi][0] = LDU(&sA[buf][0][r][k0 + 2 * tg]);
                ah[mi][1] = LDU(&sA[buf][0][r + 8][k0 + 2 * tg]);
                ah[mi][2] = LDU(&sA[buf][0][r][k0 + 2 * tg + 8]);
                ah[mi][3] = LDU(&sA[buf][0][r + 8][k0 + 2 * tg + 8]);
                al[mi][0] = LDU(&sA[buf][1][r][k0 + 2 * tg]);
                al[mi][1] = LDU(&sA[buf][1][r + 8][k0 + 2 * tg]);
                al[mi][2] = LDU(&sA[buf][1][r][k0 + 2 * tg + 8]);
                al[mi][3] = LDU(&sA[buf][1][r + 8][k0 + 2 * tg + 8]);
            }
            unsigned bh[4][2];
#pragma unroll
            for (int ni = 0; ni < 4; ni++) {
                int rn = wn + ni * 8 + g;
                bh[ni][0] = LDU(&sB[buf][rn][k0 + 2 * tg]);
                bh[ni][1] = LDU(&sB[buf][rn][k0 + 2 * tg + 8]);
            }
#pragma unroll
            for (int mi = 0; mi < 2; mi++)
#pragma unroll
                for (int ni = 0; ni < 4; ni++) {
                    MMA_F16(acc[mi][ni], ah[mi], bh[ni]);
                    MMA_F16(acc[mi][ni], al[mi], bh[ni]);
                }
        }
        __syncthreads();
    }

    const bool hasb = (jb.flags & 8), rl = (jb.flags & 1);
#pragma unroll
    for (int mi = 0; mi < 2; mi++) {
#pragma unroll
        for (int ni = 0; ni < 4; ni++) {
            int r0 = m0 + wm + mi * 16 + g;
            int r1 = r0 + 8;
            int cb = n0 + wn + ni * 8 + 2 * tg;
            float v0 = acc[mi][ni][0], v1 = acc[mi][ni][1];
            float v2 = acc[mi][ni][2], v3 = acc[mi][ni][3];
            if (hasb) {
                float b0 = jb.bias[cb], b1 = jb.bias[cb + 1];
                v0 += b0; v1 += b1; v2 += b0; v3 += b1;
            }
            if (rl) {
                v0 = fmaxf(v0, 0.f); v1 = fmaxf(v1, 0.f);
                v2 = fmaxf(v2, 0.f); v3 = fmaxf(v3, 0.f);
            }
            if (jb.flags & 2) {
                *(float2*)(jb.C + (size_t)r0 * jb.N + cb) = make_float2(v0, v1);
                *(float2*)(jb.C + (size_t)r1 * jb.N + cb) = make_float2(v2, v3);
            }
            if (jb.flags & 4) {
                __half2 h0, l0, h1, l1;
                split16(v0, h0.x, l0.x); split16(v1, h0.y, l0.y);
                split16(v2, h1.x, l1.x); split16(v3, h1.y, l1.y);
                *(__half2*)(jb.Ch + (size_t)r0 * jb.N + cb) = h0;
                *(__half2*)(jb.Cl + (size_t)r0 * jb.N + cb) = l0;
                *(__half2*)(jb.Ch + (size_t)r1 * jb.N + cb) = h1;
                *(__half2*)(jb.Cl + (size_t)r1 * jb.N + cb) = l1;
            }
        }
    }
}

// ---------------------------------------------------------------- chunk sums of H (float4, 4 row-groups x 64 lanes)
__global__ __launch_bounds__(256)
void csum_kernel(const float* __restrict__ H, float* __restrict__ CS) {
    __shared__ float4 sm[4][64];
    int b = blockIdx.x, c = blockIdx.y;
    int t = threadIdx.x;
    int d4 = t & 63;
    int rg = t >> 6;
    const float4* p = (const float4*)(H + ((long)b * SEQL + c * 64 + rg * 16) * DD) + d4;
    float4 s = make_float4(0.f, 0.f, 0.f, 0.f);
#pragma unroll
    for (int r = 0; r < 16; ++r) {
        float4 v = p[(long)r * 64];
        s.x += v.x; s.y += v.y; s.z += v.z; s.w += v.w;
    }
    sm[rg][d4] = s;
    __syncthreads();
    if (rg == 0) {
        float4 a = sm[0][d4], b1 = sm[1][d4], c1 = sm[2][d4], d1 = sm[3][d4];
        float4 o;
        o.x = (a.x + b1.x) + (c1.x + d1.x);
        o.y = (a.y + b1.y) + (c1.y + d1.y);
        o.z = (a.z + b1.z) + (c1.z + d1.z);
        o.w = (a.w + b1.w) + (c1.w + d1.w);
        ((float4*)(CS + ((long)b * 32 + c) * DD))[d4] = o;
    }
}

// ---------------------------------------------------------------- tailV[b,h,d] from chunk sums + boundary rows, fused matvec vs vW
__global__ __launch_bounds__(256)
void tailmv2_kernel(const float* __restrict__ H, const float* __restrict__ CS,
                    const float* __restrict__ vW, const float* __restrict__ vb,
                    const float* __restrict__ td, int l, float* __restrict__ tailV) {
    __shared__ float sfx[DD];
    __shared__ float red[DKK][8];
    int bh = blockIdx.x;
    int b = bh / HH, h = bh % HH;
    int tid = threadIdx.x;
    int kcut = compute_kcut(td[l * HH + h]);
    int cb = kcut >> 6;
    int cend = (cb + 1) << 6; if (cend > SEQL) cend = SEQL;
    float s = 0.f;
    for (int k = kcut; k < cend; ++k) s += H[((long)b * SEQL + k) * DD + tid];
    for (int c = cb + 1; c < 32; ++c) s += CS[((long)b * 32 + c) * DD + tid];
    sfx[tid] = s;
    __syncthreads();
    int dl = tid & 31, grp = tid >> 5;
    int n = h * DKK + dl;
    const float* w = vW + (long)l * DD * DD + (long)n * DD + grp * 32;
    const float* sv = sfx + grp * 32;
    float p = 0.f;
#pragma unroll
    for (int j = 0; j < 32; ++j) p = fmaf(sv[j], w[j], p);
    red[dl][grp] = p;
    __syncthreads();
    if (tid < DKK) {
        float t = 0.f;
#pragma unroll
        for (int gi = 0; gi < 8; gi++) t += red[tid][gi];
        tailV[bh * DKK + tid] = t + (float)(SEQL - kcut) * vb[l * DD + h * DKK + tid];
    }
}

// ---------------------------------------------------------------- attention (emits fp16 hi/lo ctx)
__global__ __launch_bounds__(128)
void attn_kernel(const float* __restrict__ Q, const float* __restrict__ Km,
                 const float* __restrict__ Vm, const float* __restrict__ td,
                 const float* __restrict__ scale, const float* __restrict__ tailV,
                 __half* __restrict__ Ch, __half* __restrict__ Cl, int l) {
    __shared__ float Ks[128][DKK];
    __shared__ float Vs[128][DKK];
    __shared__ float dec[128];
    int bh = blockIdx.y;
    int b = bh / HH, h = bh % HH;
    int tid = threadIdx.x;
    int q = blockIdx.x * 128 + tid;
    float tdh = td[l * HH + h];
    int kcut = compute_kcut(tdh);
    float c = scale[l] * rsqrtf((float)DKK);
    float4 qv[8];
    {
        const float4* qp = (const float4*)(Q + ((long)(b * SEQL + q)) * DD + h * DKK);
#pragma unroll
        for (int j = 0; j < 8; ++j) {
            float4 t = qp[j];
            t.x *= c; t.y *= c; t.z *= c; t.w *= c;
            qv[j] = t;
        }
    }
    float Z = 0.f;
    float4 cx[8];
#pragma unroll
    for (int j = 0; j < 8; ++j) cx[j] = make_float4(0.f, 0.f, 0.f, 0.f);

    for (int kb = 0; kb < kcut; kb += 128) {
        int kn = min(128, kcut - kb);
        __syncthreads();
        const float4* Kg = (const float4*)(Km + ((long)(b * SEQL + kb)) * DD + h * DKK);
        const float4* Vg = (const float4*)(Vm + ((long)(b * SEQL + kb)) * DD + h * DKK);
#pragma unroll
        for (int i = 0; i < 8; i++) {
            int idx = i * 128 + tid;
            int r = idx >> 3, c4 = idx & 7;
            if (r < kn) {
                ((float4*)Ks[r])[c4] = Kg[(long)r * (DD / 4) + c4];
                ((float4*)Vs[r])[c4] = Vg[(long)r * (DD / 4) + c4];
            }
        }
        if (tid < kn) dec[tid] = __expf(-tdh * (float)(kb + tid));
        __syncthreads();
        for (int kk = 0; kk < kn; ++kk) {
            const float4* kr = (const float4*)Ks[kk];
            float s0 = 0.f, s1 = 0.f, s2 = 0.f, s3 = 0.f;
#pragma unroll
            for (int j = 0; j < 8; j += 2) {
                float4 k0 = kr[j], k1 = kr[j + 1];
                s0 = fmaf(qv[j].x, k0.x, s0); s1 = fmaf(qv[j].y, k0.y, s1);
                s2 = fmaf(qv[j].z, k0.z, s2); s3 = fmaf(qv[j].w, k0.w, s3);
                s0 = fmaf(qv[j + 1].x, k1.x, s0); s1 = fmaf(qv[j + 1].y, k1.y, s1);
                s2 = fmaf(qv[j + 1].z, k1.z, s2); s3 = fmaf(qv[j + 1].w, k1.w, s3);
            }
            float s = ((s0 + s1) + (s2 + s3)) * dec[kk];
            float e = __expf(s);
            float w = e * e / (1.f + e);
            Z += e;
            const float4* vr = (const float4*)Vs[kk];
#pragma unroll
            for (int j = 0; j < 8; ++j) {
                float4 vv = vr[j];
                cx[j].x = fmaf(w, vv.x, cx[j].x);
                cx[j].y = fmaf(w, vv.y, cx[j].y);
                cx[j].z = fmaf(w, vv.z, cx[j].z);
                cx[j].w = fmaf(w, vv.w, cx[j].w);
            }
        }
    }
    Z += (float)(SEQL - kcut);
    float invZ = 1.f / Z;
    const float4* tv = (const float4*)(tailV + bh * DKK);
    size_t ob = ((size_t)(b * SEQL + q)) * DD + h * DKK;
#pragma unroll
    for (int j = 0; j < 8; ++j) {
        float4 t = tv[j];
        float ov[4];
        ov[0] = (cx[j].x + 0.5f * t.x) * invZ;
        ov[1] = (cx[j].y + 0.5f * t.y) * invZ;
        ov[2] = (cx[j].z + 0.5f * t.z) * invZ;
        ov[3] = (cx[j].w + 0.5f * t.w) * invZ;
#pragma unroll
        for (int u = 0; u < 4; ++u) {
            __half hh, ll;
            split16(ov[u], hh, ll);
            Ch[ob + j * 4 + u] = hh;
            Cl[ob + j * 4 + u] = ll;
        }
    }
}

// ---------------------------------------------------------------- single-query attention (layer 2 last token)
__global__ __launch_bounds__(128)
void attn1_kernel(const float* __restrict__ q2, const float* __restrict__ Km,
                  const float* __restrict__ Vm, const float* __restrict__ td,
                  const float* __restrict__ scale, const float* __restrict__ tailV,
                  float* __restrict__ ctx2, int l) {
    int b = blockIdx.x / HH, h = blockIdx.x % HH;
    int tid = threadIdx.x;
    float tdh = td[l * HH + h];
    int kcut = compute_kcut(tdh);
    float c = scale[l] * rsqrtf((float)DKK);
    __shared__ float qs[DKK];
    __shared__ float ws[128];
    __shared__ float red[4];
    if (tid < DKK) qs[tid] = q2[b * DD + h * DKK + tid] * c;
    __syncthreads();
    float Zp = 0.f;
    float cxd = 0.f;
    for (int kb = 0; kb < kcut; kb += 128) {
        int kn = min(128, kcut - kb);
        float w = 0.f;
        if (tid < kn) {
            int k = kb + tid;
            const float* kr = Km + ((long)(b * SEQL + k)) * DD + h * DKK;
            float s = 0.f;
#pragma unroll
            for (int d = 0; d < DKK; ++d) s = fmaf(qs[d], kr[d], s);
            s *= __expf(-tdh * (float)k);
            float e = __expf(s);
            w = e * e / (1.f + e);
            Zp += e;
        }
        __syncthreads();
        ws[tid] = w;
        __syncthreads();
        if (tid < DKK) {
            for (int kk = 0; kk < kn; ++kk)
                cxd = fmaf(ws[kk], Vm[((long)(b * SEQL + kb + kk)) * DD + h * DKK + tid], cxd);
        }
        __syncthreads();
    }
    float s = Zp;
#pragma unroll
    for (int o = 16; o; o >>= 1) s += __shfl_xor_sync(0xffffffffu, s, o);
    if ((tid & 31) == 0) red[tid >> 5] = s;
    __syncthreads();
    float Z = red[0] + red[1] + red[2] + red[3] + (float)(SEQL - kcut);
    if (tid < DKK)
        ctx2[b * DD + h * DKK + tid] = (cxd + 0.5f * tailV[blockIdx.x * DKK + tid]) / Z;
}

// ---------------------------------------------------------------- small-M GEMM (M=2 rows), fp32
template <bool RELU>
__global__ void rowgemm_kernel(const float* __restrict__ A, long lda,
                               const float* __restrict__ W, const float* __restrict__ bias,
                               float* __restrict__ C, int K, int N) {
    extern __shared__ float arow[];
    int m = blockIdx.x;
    int n = blockIdx.y * blockDim.x + threadIdx.x;
    for (int i = threadIdx.x; i < K; i += blockDim.x) arow[i] = A[(long)m * lda + i];
    __syncthreads();
    float s = bias[n];
    const float* wr = W + (long)n * K;
#pragma unroll 4
    for (int kk = 0; kk < K; ++kk) s = fmaf(arow[kk], wr[kk], s);
    if (RELU) s = fmaxf(s, 0.f);
    C[(long)m * N + n] = s;
}

// ---------------------------------------------------------------- residual + layernorm; optional 2nd partial + fp16 emit
template <bool TWO, bool EMIT>
__global__ void ln_kernel(const float* __restrict__ z, long zs,
                          const float* __restrict__ z2,
                          const float* __restrict__ res, long rs,
                          const float* __restrict__ g, const float* __restrict__ be,
                          float* __restrict__ out, long os,
                          __half* __restrict__ oh, __half* __restrict__ ol) {
    int m = blockIdx.x, t = threadIdx.x;
    float v = z[(long)m * zs + t] + res[(long)m * rs + t];
    if (TWO) v += z2[(long)m * zs + t];
    __shared__ float sm[8];
    float s = v;
#pragma unroll
    for (int o = 16; o; o >>= 1) s += __shfl_xor_sync(0xffffffffu, s, o);
    if ((t & 31) == 0) sm[t >> 5] = s;
    __syncthreads();
    float tot = 0.f;
#pragma unroll
    for (int i = 0; i < 8; i++) tot += sm[i];
    float mean = tot * (1.0f / DD);
    float dv = v - mean;
    float s2 = dv * dv;
    __syncthreads();
#pragma unroll
    for (int o = 16; o; o >>= 1) s2 += __shfl_xor_sync(0xffffffffu, s2, o);
    if ((t & 31) == 0) sm[t >> 5] = s2;
    __syncthreads();
    float var = 0.f;
#pragma unroll
    for (int i = 0; i < 8; i++) var += sm[i];
    var *= (1.0f / DD);
    float o = dv * rsqrtf(var + EPSF) * g[t] + be[t];
    out[(long)m * os + t] = o;
    if (EMIT) {
        __half hh, ll;
        split16(o, hh, ll);
        oh[(long)m * DD + t] = hh;
        ol[(long)m * DD + t] = ll;
    }
}

// ---------------------------------------------------------------- final projection
__global__ void out_kernel(const float* __restrict__ r2, const float* __restrict__ ow,
                           const float* __restrict__ ob, float* __restrict__ out) {
    int b = blockIdx.x, t = threadIdx.x;
    float p = r2[b * DD + t] * ow[t];
    __shared__ float sm[8];
    float s = p;
#pragma unroll
    for (int o = 16; o; o >>= 1) s += __shfl_xor_sync(0xffffffffu, s, o);
    if ((t & 31) == 0) sm[t >> 5] = s;
    __syncthreads();
    if (t == 0) {
        float tot = 0.f;
#pragma unroll
        for (int i = 0; i < 8; i++) tot += sm[i];
        out[b] = 0.5f * tot + ob[0];
    }
}

// ================================================================ host orchestration
extern "C" void kernel_launch(void* const* d_in, const int* in_sizes, int n_in,
                              void* d_out, int out_size) {
    const float* x   = (const float*)d_in[0];
    const float* cw  = (const float*)d_in[1];
    const float* cb  = (const float*)d_in[2];
    const float* bg  = (const float*)d_in[3];
    const float* bbn = (const float*)d_in[4];
    const float* pe  = (const float*)d_in[5];
    const float* qW  = (const float*)d_in[6];
    const float* qb  = (const float*)d_in[7];
    const float* kW  = (const float*)d_in[8];
    const float* kb  = (const float*)d_in[9];
    const float* vW  = (const float*)d_in[10];
    const float* vb  = (const float*)d_in[11];
    const float* oW  = (const float*)d_in[12];
    const float* ob  = (const float*)d_in[13];
    const float* scale = (const float*)d_in[14];
    const float* td  = (const float*)d_in[15];
    const float* ln1g = (const float*)d_in[16];
    const float* ln1b = (const float*)d_in[17];
    const float* f1W = (const float*)d_in[18];
    const float* f1b = (const float*)d_in[19];
    const float* f2W = (const float*)d_in[20];
    const float* f2b = (const float*)d_in[21];
    const float* ln2g = (const float*)d_in[22];
    const float* ln2b = (const float*)d_in[23];
    const float* outW = (const float*)d_in[24];
    const float* outb = (const float*)d_in[25];
    float* out = (float*)d_out;

    float* buf = nullptr;
    cudaGetSymbolAddress((void**)&buf, g_buf);
    float* H0 = buf;
    float* H2 = buf + 1L * NH;
    float* Qb = buf + 2L * NH;
    float* Kb = buf + 3L * NH;
    float* Vb = buf + 4L * NH;
    float* T  = buf + 5L * NH;
    float* TP = buf + 6L * NH;
    __half* F16 = (__half*)(buf + 7L * NH);
    __half* H0h = F16;
    __half* H0l = F16 + 1L * NH;
    __half* H2h = F16 + 2L * NH;
    __half* H2l = F16 + 3L * NH;
    __half* CXh = F16 + 4L * NH;
    __half* CXl = F16 + 5L * NH;
    __half* FFh = F16 + 6L * NH;
    __half* FFl = F16 + 6L * NH + NFF;
    __half* Wb  = F16 + 6L * NH + 2L * NFF;
    float* TAIL = buf + 7L * NH + HALF_FLOATS;
    float* SMALL = TAIL + 512;
    float* Q2 = SMALL, *CTX2 = SMALL + 512, *T2 = SMALL + 1024, *R1 = SMALL + 1536;
    float* FFROW = SMALL + 2048, *T3 = SMALL + 4096, *R2 = SMALL + 4608;
    float* CS = SMALL + 5632;   // [BB][32][DD] = 16384 floats

    // fp16 weight pointers (layer l)
    auto WQ  = [&](int l){ return Wb + 0       + l * 65536; };
    auto WK  = [&](int l){ return Wb + 131072  + l * 65536; };
    auto WV  = [&](int l){ return Wb + 262144  + l * 65536; };
    auto WO  = [&](int l){ return Wb + 393216  + l * 65536; };
    auto WF1 = [&](int l){ return Wb + 524288  + l * 262144; };
    auto WF2 = [&](int l){ return Wb + 1048576 + l * 262144; };

    const int M = BB * SEQL;                 // 4096
    dim3 gAttn(SEQL / 128, BB * HH);
    dim3 gCsum(BB, 32);

    // --- stem + weight convert ---
    conv_pe_kernel<<<(NH + 255) / 256, 256>>>(x, cw, cb, bg, bbn, pe, H0, H0h, H0l);
    wsplit_kernel<<<dim3(128, 1, 6), 256>>>(qW, kW, vW, oW, f1W, f2W, Wb);

    // --- layer 0 ---
    {   // Q full; K,V only head rows (early-exit via tdl)
        TcJobs3 J{};
        J.j[0] = {H0h, H0l, WQ(0), qb, Qb, nullptr, nullptr, nullptr, DD, DD, DD, DD, 2 | 8};
        J.j[1] = {H0h, H0l, WK(0), kb, Kb, nullptr, nullptr, td,      DD, DD, DD, DD, 2 | 8};
        J.j[2] = {H0h, H0l, WV(0), vb, Vb, nullptr, nullptr, td,      DD, DD, DD, DD, 2 | 8};
        tc_kernel<<<dim3(DD / 64, M / 128, 3), 256>>>(J);
    }
    csum_kernel<<<gCsum, 256>>>(H0, CS);
    tailmv2_kernel<<<BB * HH, 256>>>(H0, CS, vW, vb, td, 0, TAIL);
    attn_kernel<<<gAttn, 128>>>(Qb, Kb, Vb, td, scale, TAIL, CXh, CXl, 0);
    {
        TcJobs3 J{};
        J.j[0] = {CXh, CXl, WO(0), ob, T, nullptr, nullptr, nullptr, DD, DD, DD, DD, 2 | 8};
        tc_kernel<<<dim3(DD / 64, M / 128, 1), 256>>>(J);
    }
    ln_kernel<false, true><<<M, 256>>>(T, DD, nullptr, H0, DD, ln1g, ln1b, H2, DD, H2h, H2l);
    {
        TcJobs3 J{};
        J.j[0] = {H2h, H2l, WF1(0), f1b, nullptr, FFh, FFl, nullptr, DD, DD, DFFN, DD, 1 | 4 | 8};
        tc_kernel<<<dim3(DFFN / 64, M / 128, 1), 256>>>(J);
    }
    {   // FFN2 split-K=2; partials T (+bias) and TP
        TcJobs3 J{};
        J.j[0] = {FFh,       FFl,       WF2(0),       f2b, T,  nullptr, nullptr, nullptr, DFFN, DFFN, DD, 512, 2 | 8};
        J.j[1] = {FFh + 512, FFl + 512, WF2(0) + 512, f2b, TP, nullptr, nullptr, nullptr, DFFN, DFFN, DD, 512, 2};
        tc_kernel<<<dim3(DD / 64, M / 128, 2), 256>>>(J);
    }
    ln_kernel<true, true><<<M, 256>>>(T, DD, TP, H2, DD, ln2g, ln2b, H0, DD, H0h, H0l);

    // --- layer 1 (only last token needed downstream of attention) ---
    const float* qW1 = qW + DD * DD;   const float* qb1 = qb + DD;
    const float* oW1 = oW + DD * DD;   const float* ob1 = ob + DD;
    const float* kb1 = kb + DD;        const float* vb1 = vb + DD;
    const float* ln1g1 = ln1g + DD;    const float* ln1b1 = ln1b + DD;
    const float* ln2g1 = ln2g + DD;    const float* ln2b1 = ln2b + DD;
    const float* f1W1 = f1W + DFFN * DD; const float* f1b1 = f1b + DFFN;
    const float* f2W1 = f2W + DD * DFFN; const float* f2b1 = f2b + DD;
    const float* hlast = H0 + (long)(SEQL - 1) * DD;

    {   // K,V head rows only (early-exit)
        TcJobs3 J{};
        J.j[0] = {H0h, H0l, WK(1), kb1, Kb, nullptr, nullptr, td + HH, DD, DD, DD, DD, 2 | 8};
        J.j[1] = {H0h, H0l, WV(1), vb1, Vb, nullptr, nullptr, td + HH, DD, DD, DD, DD, 2 | 8};
        tc_kernel<<<dim3(DD / 64, M / 128, 2), 256>>>(J);
    }
    csum_kernel<<<gCsum, 256>>>(H0, CS);
    tailmv2_kernel<<<BB * HH, 256>>>(H0, CS, vW, vb, td, 1, TAIL);

    rowgemm_kernel<false><<<dim3(BB, 1), 256, DD * 4>>>(hlast, (long)SEQL * DD, qW1, qb1, Q2, DD, DD);
    attn1_kernel<<<BB * HH, 128>>>(Q2, Kb, Vb, td, scale, TAIL, CTX2, 1);
    rowgemm_kernel<false><<<dim3(BB, 1), 256, DD * 4>>>(CTX2, DD, oW1, ob1, T2, DD, DD);
    ln_kernel<false, false><<<BB, 256>>>(T2, DD, nullptr, hlast, (long)SEQL * DD, ln1g1, ln1b1, R1, DD, nullptr, nullptr);
    rowgemm_kernel<true ><<<dim3(BB, DFFN / 256), 256, DD * 4>>>(R1, DD, f1W1, f1b1, FFROW, DD, DFFN);
    rowgemm_kernel<false><<<dim3(BB, 1), 256, DFFN * 4>>>(FFROW, DFFN, f2W1, f2b1, T3, DFFN, DD);
    ln_kernel<false, false><<<BB, 256>>>(T3, DD, nullptr, R1, DD, ln2g1, ln2b1, R2, DD, nullptr, nullptr);

    out_kernel<<<BB, 256>>>(R2, outW, outb, out);
}

// round 12
// speedup vs baseline: 1.8238x; 1.0011x over previous
#include <cuda_runtime.h>
#include <cuda_fp16.h>

#define BB 2
#define SEQL 2048
#define DD 256
#define HH 8
#define DKK 32
#define DFFN 1024
#define EPSF 1e-5f

#define NH  (BB*SEQL*DD)      /* 1048576 */
#define NFF (BB*SEQL*DFFN)    /* 4194304 */

#define HALF_FLOATS 8912896L
__device__ float g_buf[7L*NH + HALF_FLOATS + 512 + 32768];

__device__ __forceinline__ int compute_kcut(float tdh) {
    if (!(tdh > 1e-6f)) return SEQL;
    float c = 33.0f / tdh;     // exp(s * e^-33) == 1.0f exactly for |s| < 1e7
    if (c >= (float)SEQL) return SEQL;
    int k = (int)ceilf(c);
    return k < SEQL ? k : SEQL;
}

// ---------------------------------------------------------------- cp.async helpers
#define CP16(dst, src) \
    asm volatile("cp.async.cg.shared.global [%0], [%1], 16;" :: "r"(dst), "l"(src))
#define CPCOMMIT() asm volatile("cp.async.commit_group;" ::: "memory")
#define CPWAIT0() asm volatile("cp.async.wait_group 0;" ::: "memory")
#define CPWAIT1() asm volatile("cp.async.wait_group 1;" ::: "memory")

#define LDSM4(r0, r1, r2, r3, addr) \
    asm volatile("ldmatrix.sync.aligned.m8n8.x4.shared.b16 {%0,%1,%2,%3}, [%4];" \
        : "=r"(r0), "=r"(r1), "=r"(r2), "=r"(r3) : "r"(addr))

__device__ __forceinline__ void split16(float x, __half& h, __half& l) {
    h = __float2half(x);
    l = __float2half(x - __half2float(h));
}

// ---------------------------------------------------------------- conv + bn + relu + pe (+ fp16 split)
__global__ void conv_pe_kernel(const float* __restrict__ x, const float* __restrict__ cw,
                               const float* __restrict__ cb, const float* __restrict__ bg,
                               const float* __restrict__ bb, const float* __restrict__ pe,
                               float* __restrict__ out,
                               __half* __restrict__ oh, __half* __restrict__ ol) {
    int idx = blockIdx.x * 256 + threadIdx.x;
    if (idx >= NH) return;
    int d = idx & (DD - 1);
    int t = (idx >> 8) & (SEQL - 1);
    int b = idx >> 19;
    const float* xb = x + b * SEQL;
    float xm = t > 0 ? xb[t - 1] : 0.f;
    float x0 = xb[t];
    float xp = (t < SEQL - 1) ? xb[t + 1] : 0.f;
    float v = cw[d * 3 + 0] * xm + cw[d * 3 + 1] * x0 + cw[d * 3 + 2] * xp + cb[d];
    v = v * rsqrtf(1.f + EPSF) * bg[d] + bb[d];
    v = fmaxf(v, 0.f);
    float r = v + pe[t * DD + d];
    out[idx] = r;
    __half h, l;
    split16(r, h, l);
    oh[idx] = h;
    ol[idx] = l;
}

// ---------------------------------------------------------------- weight convert fp32 -> fp16 (single)
__global__ void wsplit_kernel(const float* __restrict__ q, const float* __restrict__ k,
                              const float* __restrict__ v, const float* __restrict__ o,
                              const float* __restrict__ f1, const float* __restrict__ f2,
                              __half* __restrict__ W) {
    int z = blockIdx.z;
    const float* src; long n; long off;
    switch (z) {
        case 0: src = q;  n = 131072; off = 0;       break;
        case 1: src = k;  n = 131072; off = 131072;  break;
        case 2: src = v;  n = 131072; off = 262144;  break;
        case 3: src = o;  n = 131072; off = 393216;  break;
        case 4: src = f1; n = 524288; off = 524288;  break;
        default: src = f2; n = 524288; off = 1048576; break;
    }
    __half* dh = W + off;
    for (long i = blockIdx.x * 256L + threadIdx.x; i < n; i += (long)gridDim.x * 256L)
        dh[i] = __float2half(src[i]);
}

// ---------------------------------------------------------------- HMMA GEMM: C[M,N] = A[M,K] @ W[N,K]^T
// A as fp16 hi/lo split (2-pass), W single fp16; fp32 accumulate. ldmatrix fragment loads.
struct TcJob {
    const __half *Ah, *Al;
    const __half *Wh;
    const float* bias;
    float* C;
    __half *Ch, *Cl;
    const float* tdl;            // if set: CTA exits when (m0 & (SEQL-1)) >= max kcut
    int lda, ldw, N, K, flags;   // flags: 1=RELU 2=FP32OUT 4=F16OUT 8=BIAS
};
struct TcJobs3 { TcJob j[3]; };

#define MMA_F16(c, a, b) \
    asm volatile("mma.sync.aligned.m16n8k16.row.col.f32.f16.f16.f32 " \
        "{%0,%1,%2,%3}, {%4,%5,%6,%7}, {%8,%9}, {%0,%1,%2,%3};" \
        : "+f"((c)[0]), "+f"((c)[1]), "+f"((c)[2]), "+f"((c)[3]) \
        : "r"((a)[0]), "r"((a)[1]), "r"((a)[2]), "r"((a)[3]), "r"((b)[0]), "r"((b)[1]))

__global__ __launch_bounds__(256) void tc_kernel(TcJobs3 jobs) {
    TcJob jb = jobs.j[blockIdx.z];
    const int m0 = blockIdx.y * 128, n0 = blockIdx.x * 64;
    if (jb.tdl) {
        int kmax = 0;
#pragma unroll
        for (int h = 0; h < HH; h++) {
            int kc = compute_kcut(jb.tdl[h]);
            kmax = kc > kmax ? kc : kmax;
        }
        if ((m0 & (SEQL - 1)) >= kmax) return;   // rows unused downstream
    }
    __shared__ __half sA[2][2][128][40];   // [stage][hi/lo][row][k+pad]
    __shared__ __half sB[2][64][40];       // [stage][row][k+pad]
    const int tid = threadIdx.x, wid = tid >> 5, lane = tid & 31;
    const int wm = (wid & 3) * 32, wn = (wid >> 2) * 32;
    const int g = lane >> 2, tg = lane & 3;
    const int lmrow = lane & 15, lmcol = (lane >> 4) * 8;   // ldmatrix addressing

    float acc[2][4][4];
#pragma unroll
    for (int mi = 0; mi < 2; mi++)
#pragma unroll
        for (int ni = 0; ni < 4; ni++)
#pragma unroll
            for (int r = 0; r < 4; r++) acc[mi][ni][r] = 0.f;

    const int brow = tid >> 2, bc8 = tid & 3;
    const int nkb = jb.K >> 5;

    auto issue = [&](int it) {
        const int buf = it & 1;
        const int kb = it << 5;
#pragma unroll
        for (int i = 0; i < 2; i++) {
            int idx = i * 256 + tid;
            int rr = idx >> 2, cc = idx & 3;
            size_t go = (size_t)(m0 + rr) * jb.lda + kb + cc * 8;
            CP16((unsigned)__cvta_generic_to_shared(&sA[buf][0][rr][cc * 8]), jb.Ah + go);
            CP16((unsigned)__cvta_generic_to_shared(&sA[buf][1][rr][cc * 8]), jb.Al + go);
        }
        {
            size_t go = (size_t)(n0 + brow) * jb.ldw + kb + bc8 * 8;
            CP16((unsigned)__cvta_generic_to_shared(&sB[buf][brow][bc8 * 8]), jb.Wh + go);
        }
        CPCOMMIT();
    };

    issue(0);
    for (int it = 0; it < nkb; ++it) {
        const int buf = it & 1;
        if (it + 1 < nkb) {
            issue(it + 1);
            CPWAIT1();
        } else {
            CPWAIT0();
        }
        __syncthreads();

#pragma unroll
        for (int ks = 0; ks < 2; ks++) {
            const int k0 = ks * 16;
            unsigned ah[2][4], al[2][4], bh[4][2];
#pragma unroll
            for (int mi = 0; mi < 2; mi++) {
                unsigned ad = (unsigned)__cvta_generic_to_shared(
                    &sA[buf][0][wm + mi * 16 + lmrow][k0 + lmcol]);
                LDSM4(ah[mi][0], ah[mi][1], ah[mi][2], ah[mi][3], ad);
                unsigned ad2 = (unsigned)__cvta_generic_to_shared(
                    &sA[buf][1][wm + mi * 16 + lmrow][k0 + lmcol]);
                LDSM4(al[mi][0], al[mi][1], al[mi][2], al[mi][3], ad2);
            }
#pragma unroll
            for (int np = 0; np < 2; np++) {
                unsigned bd = (unsigned)__cvta_generic_to_shared(
                    &sB[buf][wn + np * 16 + lmrow][k0 + lmcol]);
                unsigned t0, t1, t2, t3;
                LDSM4(t0, t1, t2, t3, bd);
                bh[np * 2 + 0][0] = t0; bh[np * 2 + 0][1] = t2;
                bh[np * 2 + 1][0] = t1; bh[np * 2 + 1][1] = t3;
            }
#pragma unroll
            for (int mi = 0; mi < 2; mi++)
#pragma unroll
                for (int ni = 0; ni < 4; ni++) {
                    MMA_F16(acc[mi][ni], ah[mi], bh[ni]);
                    MMA_F16(acc[mi][ni], al[mi], bh[ni]);
                }
        }
        __syncthreads();
    }

    const bool hasb = (jb.flags & 8), rl = (jb.flags & 1);
#pragma unroll
    for (int mi = 0; mi < 2; mi++) {
#pragma unroll
        for (int ni = 0; ni < 4; ni++) {
            int r0 = m0 + wm + mi * 16 + g;
            int r1 = r0 + 8;
            int cb = n0 + wn + ni * 8 + 2 * tg;
            float v0 = acc[mi][ni][0], v1 = acc[mi][ni][1];
            float v2 = acc[mi][ni][2], v3 = acc[mi][ni][3];
            if (hasb) {
                float b0 = jb.bias[cb], b1 = jb.bias[cb + 1];
                v0 += b0; v1 += b1; v2 += b0; v3 += b1;
            }
            if (rl) {
                v0 = fmaxf(v0, 0.f); v1 = fmaxf(v1, 0.f);
                v2 = fmaxf(v2, 0.f); v3 = fmaxf(v3, 0.f);
            }
            if (jb.flags & 2) {
                *(float2*)(jb.C + (size_t)r0 * jb.N + cb) = make_float2(v0, v1);
                *(float2*)(jb.C + (size_t)r1 * jb.N + cb) = make_float2(v2, v3);
            }
            if (jb.flags & 4) {
                __half2 h0, l0, h1, l1;
                split16(v0, h0.x, l0.x); split16(v1, h0.y, l0.y);
                split16(v2, h1.x, l1.x); split16(v3, h1.y, l1.y);
                *(__half2*)(jb.Ch + (size_t)r0 * jb.N + cb) = h0;
                *(__half2*)(jb.Cl + (size_t)r0 * jb.N + cb) = l0;
                *(__half2*)(jb.Ch + (size_t)r1 * jb.N + cb) = h1;
                *(__half2*)(jb.Cl + (size_t)r1 * jb.N + cb) = l1;
            }
        }
    }
}

// ---------------------------------------------------------------- chunk sums of H (float4, 4 row-groups x 64 lanes)
__global__ __launch_bounds__(256)
void csum_kernel(const float* __restrict__ H, float* __restrict__ CS) {
    __shared__ float4 sm[4][64];
    int b = blockIdx.x, c = blockIdx.y;
    int t = threadIdx.x;
    int d4 = t & 63;
    int rg = t >> 6;
    const float4* p = (const float4*)(H + ((long)b * SEQL + c * 64 + rg * 16) * DD) + d4;
    float4 s = make_float4(0.f, 0.f, 0.f, 0.f);
#pragma unroll
    for (int r = 0; r < 16; ++r) {
        float4 v = p[(long)r * 64];
        s.x += v.x; s.y += v.y; s.z += v.z; s.w += v.w;
    }
    sm[rg][d4] = s;
    __syncthreads();
    if (rg == 0) {
        float4 a = sm[0][d4], b1 = sm[1][d4], c1 = sm[2][d4], d1 = sm[3][d4];
        float4 o;
        o.x = (a.x + b1.x) + (c1.x + d1.x);
        o.y = (a.y + b1.y) + (c1.y + d1.y);
        o.z = (a.z + b1.z) + (c1.z + d1.z);
        o.w = (a.w + b1.w) + (c1.w + d1.w);
        ((float4*)(CS + ((long)b * 32 + c) * DD))[d4] = o;
    }
}

// ---------------------------------------------------------------- tailV[b,h,d] from chunk sums + boundary rows, fused matvec vs vW
__global__ __launch_bounds__(256)
void tailmv2_kernel(const float* __restrict__ H, const float* __restrict__ CS,
                    const float* __restrict__ vW, const float* __restrict__ vb,
                    const float* __restrict__ td, int l, float* __restrict__ tailV) {
    __shared__ float sfx[DD];
    __shared__ float red[DKK][8];
    int bh = blockIdx.x;
    int b = bh / HH, h = bh % HH;
    int tid = threadIdx.x;
    int kcut = compute_kcut(td[l * HH + h]);
    int cb = kcut >> 6;
    int cend = (cb + 1) << 6; if (cend > SEQL) cend = SEQL;
    float s = 0.f;
    for (int k = kcut; k < cend; ++k) s += H[((long)b * SEQL + k) * DD + tid];
    for (int c = cb + 1; c < 32; ++c) s += CS[((long)b * 32 + c) * DD + tid];
    sfx[tid] = s;
    __syncthreads();
    int dl = tid & 31, grp = tid >> 5;
    int n = h * DKK + dl;
    const float* w = vW + (long)l * DD * DD + (long)n * DD + grp * 32;
    const float* sv = sfx + grp * 32;
    float p = 0.f;
#pragma unroll
    for (int j = 0; j < 32; ++j) p = fmaf(sv[j], w[j], p);
    red[dl][grp] = p;
    __syncthreads();
    if (tid < DKK) {
        float t = 0.f;
#pragma unroll
        for (int gi = 0; gi < 8; gi++) t += red[tid][gi];
        tailV[bh * DKK + tid] = t + (float)(SEQL - kcut) * vb[l * DD + h * DKK + tid];
    }
}

// ---------------------------------------------------------------- attention (emits fp16 hi/lo ctx)
__global__ __launch_bounds__(128)
void attn_kernel(const float* __restrict__ Q, const float* __restrict__ Km,
                 const float* __restrict__ Vm, const float* __restrict__ td,
                 const float* __restrict__ scale, const float* __restrict__ tailV,
                 __half* __restrict__ Ch, __half* __restrict__ Cl, int l) {
    __shared__ float Ks[128][DKK];
    __shared__ float Vs[128][DKK];
    __shared__ float dec[128];
    int bh = blockIdx.y;
    int b = bh / HH, h = bh % HH;
    int tid = threadIdx.x;
    int q = blockIdx.x * 128 + tid;
    float tdh = td[l * HH + h];
    int kcut = compute_kcut(tdh);
    float c = scale[l] * rsqrtf((float)DKK);
    float4 qv[8];
    {
        const float4* qp = (const float4*)(Q + ((long)(b * SEQL + q)) * DD + h * DKK);
#pragma unroll
        for (int j = 0; j < 8; ++j) {
            float4 t = qp[j];
            t.x *= c; t.y *= c; t.z *= c; t.w *= c;
            qv[j] = t;
        }
    }
    float Z = 0.f;
    float4 cx[8];
#pragma unroll
    for (int j = 0; j < 8; ++j) cx[j] = make_float4(0.f, 0.f, 0.f, 0.f);

    for (int kb = 0; kb < kcut; kb += 128) {
        int kn = min(128, kcut - kb);
        __syncthreads();
        const float4* Kg = (const float4*)(Km + ((long)(b * SEQL + kb)) * DD + h * DKK);
        const float4* Vg = (const float4*)(Vm + ((long)(b * SEQL + kb)) * DD + h * DKK);
#pragma unroll
        for (int i = 0; i < 8; i++) {
            int idx = i * 128 + tid;
            int r = idx >> 3, c4 = idx & 7;
            if (r < kn) {
                ((float4*)Ks[r])[c4] = Kg[(long)r * (DD / 4) + c4];
                ((float4*)Vs[r])[c4] = Vg[(long)r * (DD / 4) + c4];
            }
        }
        if (tid < kn) dec[tid] = __expf(-tdh * (float)(kb + tid));
        __syncthreads();
        for (int kk = 0; kk < kn; ++kk) {
            const float4* kr = (const float4*)Ks[kk];
            float s0 = 0.f, s1 = 0.f, s2 = 0.f, s3 = 0.f;
#pragma unroll
            for (int j = 0; j < 8; j += 2) {
                float4 k0 = kr[j], k1 = kr[j + 1];
                s0 = fmaf(qv[j].x, k0.x, s0); s1 = fmaf(qv[j].y, k0.y, s1);
                s2 = fmaf(qv[j].z, k0.z, s2); s3 = fmaf(qv[j].w, k0.w, s3);
                s0 = fmaf(qv[j + 1].x, k1.x, s0); s1 = fmaf(qv[j + 1].y, k1.y, s1);
                s2 = fmaf(qv[j + 1].z, k1.z, s2); s3 = fmaf(qv[j + 1].w, k1.w, s3);
            }
            float s = ((s0 + s1) + (s2 + s3)) * dec[kk];
            float e = __expf(s);
            float w = e * e / (1.f + e);
            Z += e;
            const float4* vr = (const float4*)Vs[kk];
#pragma unroll
            for (int j = 0; j < 8; ++j) {
                float4 vv = vr[j];
                cx[j].x = fmaf(w, vv.x, cx[j].x);
                cx[j].y = fmaf(w, vv.y, cx[j].y);
                cx[j].z = fmaf(w, vv.z, cx[j].z);
                cx[j].w = fmaf(w, vv.w, cx[j].w);
            }
        }
    }
    Z += (float)(SEQL - kcut);
    float invZ = 1.f / Z;
    const float4* tv = (const float4*)(tailV + bh * DKK);
    size_t ob = ((size_t)(b * SEQL + q)) * DD + h * DKK;
#pragma unroll
    for (int j = 0; j < 8; ++j) {
        float4 t = tv[j];
        float ov[4];
        ov[0] = (cx[j].x + 0.5f * t.x) * invZ;
        ov[1] = (cx[j].y + 0.5f * t.y) * invZ;
        ov[2] = (cx[j].z + 0.5f * t.z) * invZ;
        ov[3] = (cx[j].w + 0.5f * t.w) * invZ;
#pragma unroll
        for (int u = 0; u < 4; ++u) {
            __half hh, ll;
            split16(ov[u], hh, ll);
            Ch[ob + j * 4 + u] = hh;
            Cl[ob + j * 4 + u] = ll;
        }
    }
}

// ---------------------------------------------------------------- single-query attention (layer 2 last token)
__global__ __launch_bounds__(128)
void attn1_kernel(const float* __restrict__ q2, const float* __restrict__ Km,
                  const float* __restrict__ Vm, const float* __restrict__ td,
                  const float* __restrict__ scale, const float* __restrict__ tailV,
                  float* __restrict__ ctx2, int l) {
    int b = blockIdx.x / HH, h = blockIdx.x % HH;
    int tid = threadIdx.x;
    float tdh = td[l * HH + h];
    int kcut = compute_kcut(tdh);
    float c = scale[l] * rsqrtf((float)DKK);
    __shared__ float qs[DKK];
    __shared__ float ws[128];
    __shared__ float red[4];
    if (tid < DKK) qs[tid] = q2[b * DD + h * DKK + tid] * c;
    __syncthreads();
    float Zp = 0.f;
    float cxd = 0.f;
    for (int kb = 0; kb < kcut; kb += 128) {
        int kn = min(128, kcut - kb);
        float w = 0.f;
        if (tid < kn) {
            int k = kb + tid;
            const float* kr = Km + ((long)(b * SEQL + k)) * DD + h * DKK;
            float s = 0.f;
#pragma unroll
            for (int d = 0; d < DKK; ++d) s = fmaf(qs[d], kr[d], s);
            s *= __expf(-tdh * (float)k);
            float e = __expf(s);
            w = e * e / (1.f + e);
            Zp += e;
        }
        __syncthreads();
        ws[tid] = w;
        __syncthreads();
        if (tid < DKK) {
            for (int kk = 0; kk < kn; ++kk)
                cxd = fmaf(ws[kk], Vm[((long)(b * SEQL + kb + kk)) * DD + h * DKK + tid], cxd);
        }
        __syncthreads();
    }
    float s = Zp;
#pragma unroll
    for (int o = 16; o; o >>= 1) s += __shfl_xor_sync(0xffffffffu, s, o);
    if ((tid & 31) == 0) red[tid >> 5] = s;
    __syncthreads();
    float Z = red[0] + red[1] + red[2] + red[3] + (float)(SEQL - kcut);
    if (tid < DKK)
        ctx2[b * DD + h * DKK + tid] = (cxd + 0.5f * tailV[blockIdx.x * DKK + tid]) / Z;
}

// ---------------------------------------------------------------- small-M GEMM (M=2 rows), fp32
template <bool RELU>
__global__ void rowgemm_kernel(const float* __restrict__ A, long lda,
                               const float* __restrict__ W, const float* __restrict__ bias,
                               float* __restrict__ C, int K, int N) {
    extern __shared__ float arow[];
    int m = blockIdx.x;
    int n = blockIdx.y * blockDim.x + threadIdx.x;
    for (int i = threadIdx.x; i < K; i += blockDim.x) arow[i] = A[(long)m * lda + i];
    __syncthreads();
    float s = bias[n];
    const float* wr = W + (long)n * K;
#pragma unroll 4
    for (int kk = 0; kk < K; ++kk) s = fmaf(arow[kk], wr[kk], s);
    if (RELU) s = fmaxf(s, 0.f);
    C[(long)m * N + n] = s;
}

// ---------------------------------------------------------------- residual + layernorm; optional 2nd partial + fp16 emit
template <bool TWO, bool EMIT>
__global__ void ln_kernel(const float* __restrict__ z, long zs,
                          const float* __restrict__ z2,
                          const float* __restrict__ res, long rs,
                          const float* __restrict__ g, const float* __restrict__ be,
                          float* __restrict__ out, long os,
                          __half* __restrict__ oh, __half* __restrict__ ol) {
    int m = blockIdx.x, t = threadIdx.x;
    float v = z[(long)m * zs + t] + res[(long)m * rs + t];
    if (TWO) v += z2[(long)m * zs + t];
    __shared__ float sm[8];
    float s = v;
#pragma unroll
    for (int o = 16; o; o >>= 1) s += __shfl_xor_sync(0xffffffffu, s, o);
    if ((t & 31) == 0) sm[t >> 5] = s;
    __syncthreads();
    float tot = 0.f;
#pragma unroll
    for (int i = 0; i < 8; i++) tot += sm[i];
    float mean = tot * (1.0f / DD);
    float dv = v - mean;
    float s2 = dv * dv;
    __syncthreads();
#pragma unroll
    for (int o = 16; o; o >>= 1) s2 += __shfl_xor_sync(0xffffffffu, s2, o);
    if ((t & 31) == 0) sm[t >> 5] = s2;
    __syncthreads();
    float var = 0.f;
#pragma unroll
    for (int i = 0; i < 8; i++) var += sm[i];
    var *= (1.0f / DD);
    float o = dv * rsqrtf(var + EPSF) * g[t] + be[t];
    out[(long)m * os + t] = o;
    if (EMIT) {
        __half hh, ll;
        split16(o, hh, ll);
        oh[(long)m * DD + t] = hh;
        ol[(long)m * DD + t] = ll;
    }
}

// ---------------------------------------------------------------- final projection
__global__ void out_kernel(const float* __restrict__ r2, const float* __restrict__ ow,
                           const float* __restrict__ ob, float* __restrict__ out) {
    int b = blockIdx.x, t = threadIdx.x;
    float p = r2[b * DD + t] * ow[t];
    __shared__ float sm[8];
    float s = p;
#pragma unroll
    for (int o = 16; o; o >>= 1) s += __shfl_xor_sync(0xffffffffu, s, o);
    if ((t & 31) == 0) sm[t >> 5] = s;
    __syncthreads();
    if (t == 0) {
        float tot = 0.f;
#pragma unroll
        for (int i = 0; i < 8; i++) tot += sm[i];
        out[b] = 0.5f * tot + ob[0];
    }
}

// ================================================================ host orchestration
extern "C" void kernel_launch(void* const* d_in, const int* in_sizes, int n_in,
                              void* d_out, int out_size) {
    const float* x   = (const float*)d_in[0];
    const float* cw  = (const float*)d_in[1];
    const float* cb  = (const float*)d_in[2];
    const float* bg  = (const float*)d_in[3];
    const float* bbn = (const float*)d_in[4];
    const float* pe  = (const float*)d_in[5];
    const float* qW  = (const float*)d_in[6];
    const float* qb  = (const float*)d_in[7];
    const float* kW  = (const float*)d_in[8];
    const float* kb  = (const float*)d_in[9];
    const float* vW  = (const float*)d_in[10];
    const float* vb  = (const float*)d_in[11];
    const float* oW  = (const float*)d_in[12];
    const float* ob  = (const float*)d_in[13];
    const float* scale = (const float*)d_in[14];
    const float* td  = (const float*)d_in[15];
    const float* ln1g = (const float*)d_in[16];
    const float* ln1b = (const float*)d_in[17];
    const float* f1W = (const float*)d_in[18];
    const float* f1b = (const float*)d_in[19];
    const float* f2W = (const float*)d_in[20];
    const float* f2b = (const float*)d_in[21];
    const float* ln2g = (const float*)d_in[22];
    const float* ln2b = (const float*)d_in[23];
    const float* outW = (const float*)d_in[24];
    const float* outb = (const float*)d_in[25];
    float* out = (float*)d_out;

    float* buf = nullptr;
    cudaGetSymbolAddress((void**)&buf, g_buf);
    float* H0 = buf;
    float* H2 = buf + 1L * NH;
    float* Qb = buf + 2L * NH;
    float* Kb = buf + 3L * NH;
    float* Vb = buf + 4L * NH;
    float* T  = buf + 5L * NH;
    float* TP = buf + 6L * NH;
    __half* F16 = (__half*)(buf + 7L * NH);
    __half* H0h = F16;
    __half* H0l = F16 + 1L * NH;
    __half* H2h = F16 + 2L * NH;
    __half* H2l = F16 + 3L * NH;
    __half* CXh = F16 + 4L * NH;
    __half* CXl = F16 + 5L * NH;
    __half* FFh = F16 + 6L * NH;
    __half* FFl = F16 + 6L * NH + NFF;
    __half* Wb  = F16 + 6L * NH + 2L * NFF;
    float* TAIL = buf + 7L * NH + HALF_FLOATS;
    float* SMALL = TAIL + 512;
    float* Q2 = SMALL, *CTX2 = SMALL + 512, *T2 = SMALL + 1024, *R1 = SMALL + 1536;
    float* FFROW = SMALL + 2048, *T3 = SMALL + 4096, *R2 = SMALL + 4608;
    float* CS = SMALL + 5632;   // [BB][32][DD] = 16384 floats

    auto WQ  = [&](int l){ return Wb + 0       + l * 65536; };
    auto WK  = [&](int l){ return Wb + 131072  + l * 65536; };
    auto WV  = [&](int l){ return Wb + 262144  + l * 65536; };
    auto WO  = [&](int l){ return Wb + 393216  + l * 65536; };
    auto WF1 = [&](int l){ return Wb + 524288  + l * 262144; };
    auto WF2 = [&](int l){ return Wb + 1048576 + l * 262144; };

    const int M = BB * SEQL;                 // 4096
    dim3 gAttn(SEQL / 128, BB * HH);
    dim3 gCsum(BB, 32);

    // --- stem + weight convert ---
    conv_pe_kernel<<<(NH + 255) / 256, 256>>>(x, cw, cb, bg, bbn, pe, H0, H0h, H0l);
    wsplit_kernel<<<dim3(128, 1, 6), 256>>>(qW, kW, vW, oW, f1W, f2W, Wb);

    // --- layer 0 ---
    {   // Q full; K,V only head rows (early-exit via tdl)
        TcJobs3 J{};
        J.j[0] = {H0h, H0l, WQ(0), qb, Qb, nullptr, nullptr, nullptr, DD, DD, DD, DD, 2 | 8};
        J.j[1] = {H0h, H0l, WK(0), kb, Kb, nullptr, nullptr, td,      DD, DD, DD, DD, 2 | 8};
        J.j[2] = {H0h, H0l, WV(0), vb, Vb, nullptr, nullptr, td,      DD, DD, DD, DD, 2 | 8};
        tc_kernel<<<dim3(DD / 64, M / 128, 3), 256>>>(J);
    }
    csum_kernel<<<gCsum, 256>>>(H0, CS);
    tailmv2_kernel<<<BB * HH, 256>>>(H0, CS, vW, vb, td, 0, TAIL);
    attn_kernel<<<gAttn, 128>>>(Qb, Kb, Vb, td, scale, TAIL, CXh, CXl, 0);
    {
        TcJobs3 J{};
        J.j[0] = {CXh, CXl, WO(0), ob, T, nullptr, nullptr, nullptr, DD, DD, DD, DD, 2 | 8};
        tc_kernel<<<dim3(DD / 64, M / 128, 1), 256>>>(J);
    }
    ln_kernel<false, true><<<M, 256>>>(T, DD, nullptr, H0, DD, ln1g, ln1b, H2, DD, H2h, H2l);
    {
        TcJobs3 J{};
        J.j[0] = {H2h, H2l, WF1(0), f1b, nullptr, FFh, FFl, nullptr, DD, DD, DFFN, DD, 1 | 4 | 8};
        tc_kernel<<<dim3(DFFN / 64, M / 128, 1), 256>>>(J);
    }
    {   // FFN2 split-K=2; partials T (+bias) and TP
        TcJobs3 J{};
        J.j[0] = {FFh,       FFl,       WF2(0),       f2b, T,  nullptr, nullptr, nullptr, DFFN, DFFN, DD, 512, 2 | 8};
        J.j[1] = {FFh + 512, FFl + 512, WF2(0) + 512, f2b, TP, nullptr, nullptr, nullptr, DFFN, DFFN, DD, 512, 2};
        tc_kernel<<<dim3(DD / 64, M / 128, 2), 256>>>(J);
    }
    ln_kernel<true, true><<<M, 256>>>(T, DD, TP, H2, DD, ln2g, ln2b, H0, DD, H0h, H0l);

    // --- layer 1 (only last token needed downstream of attention) ---
    const float* qW1 = qW + DD * DD;   const float* qb1 = qb + DD;
    const float* oW1 = oW + DD * DD;   const float* ob1 = ob + DD;
    const float* kb1 = kb + DD;        const float* vb1 = vb + DD;
    const float* ln1g1 = ln1g + DD;    const float* ln1b1 = ln1b + DD;
    const float* ln2g1 = ln2g + DD;    const float* ln2b1 = ln2b + DD;
    const float* f1W1 = f1W + DFFN * DD; const float* f1b1 = f1b + DFFN;
    const float* f2W1 = f2W + DD * DFFN; const float* f2b1 = f2b + DD;
    const float* hlast = H0 + (long)(SEQL - 1) * DD;

    {   // K,V head rows only (early-exit)
        TcJobs3 J{};
        J.j[0] = {H0h, H0l, WK(1), kb1, Kb, nullptr, nullptr, td + HH, DD, DD, DD, DD, 2 | 8};
        J.j[1] = {H0h, H0l, WV(1), vb1, Vb, nullptr, nullptr, td + HH, DD, DD, DD, DD, 2 | 8};
        tc_kernel<<<dim3(DD / 64, M / 128, 2), 256>>>(J);
    }
    csum_kernel<<<gCsum, 256>>>(H0, CS);
    tailmv2_kernel<<<BB * HH, 256>>>(H0, CS, vW, vb, td, 1, TAIL);

    rowgemm_kernel<false><<<dim3(BB, 1), 256, DD * 4>>>(hlast, (long)SEQL * DD, qW1, qb1, Q2, DD, DD);
    attn1_kernel<<<BB * HH, 128>>>(Q2, Kb, Vb, td, scale, TAIL, CTX2, 1);
    rowgemm_kernel<false><<<dim3(BB, 1), 256, DD * 4>>>(CTX2, DD, oW1, ob1, T2, DD, DD);
    ln_kernel<false, false><<<BB, 256>>>(T2, DD, nullptr, hlast, (long)SEQL * DD, ln1g1, ln1b1, R1, DD, nullptr, nullptr);
    rowgemm_kernel<true ><<<dim3(BB, DFFN / 256), 256, DD * 4>>>(R1, DD, f1W1, f1b1, FFROW, DD, DFFN);
    rowgemm_kernel<false><<<dim3(BB, 1), 256, DFFN * 4>>>(FFROW, DFFN, f2W1, f2b1, T3, DFFN, DD);
    ln_kernel<false, false><<<BB, 256>>>(T3, DD, nullptr, R1, DD, ln2g1, ln2b1, R2, DD, nullptr, nullptr);

    out_kernel<<<BB, 256>>>(R2, outW, outb, out);
}